// round 11
// baseline (speedup 1.0000x reference)
#include <cuda_runtime.h>
#include <math_constants.h>

#define BS   1024
#define DM   512
#define NH   8
#define DK   64
#define HIST 199
#define TT   200
#define TTILE 2
#define NBUF 6
#define NTILES 100

// Scratch — referenced ONLY inside device code (host-side use passes the host
// shadow address; ATS makes it silently dereferenceable -> garbage).
__device__ float g_q[BS * DM];        // 2 MB
__device__ float g_r[BS * NH * DM];   // 16 MB
__device__ float g_c[BS * NH * DM];   // 16 MB

typedef unsigned long long u64;

// ---- packed f32x2 helpers --------------------------------------------------
__device__ __forceinline__ u64 pack2(float x, float y) {
    u64 r; asm("mov.b64 %0, {%1, %2};" : "=l"(r) : "f"(x), "f"(y)); return r;
}
__device__ __forceinline__ float2 unpack2(u64 v) {
    float2 d; asm("mov.b64 {%0, %1}, %2;" : "=f"(d.x), "=f"(d.y) : "l"(v)); return d;
}
__device__ __forceinline__ void ffma2(u64& acc, u64 a, u64 b) {
    asm("fma.rn.f32x2 %0, %1, %2, %0;" : "+l"(acc) : "l"(a), "l"(b));
}
__device__ __forceinline__ void fmul2(u64& a, u64 b) {
    asm("mul.rn.f32x2 %0, %0, %1;" : "+l"(a) : "l"(b));
}
__device__ __forceinline__ void cp16(void* smem_dst, const void* gsrc) {
    unsigned s = (unsigned)__cvta_generic_to_shared(smem_dst);
    asm volatile("cp.async.cg.shared.global [%0], [%1], 16;" :: "r"(s), "l"(gsrc));
}
__device__ __forceinline__ void cp_commit() { asm volatile("cp.async.commit_group;" ::: "memory"); }
__device__ __forceinline__ void cp_wait4()  { asm volatile("cp.async.wait_group 4;" ::: "memory"); }
__device__ __forceinline__ void cp_wait1()  { asm volatile("cp.async.wait_group 1;" ::: "memory"); }

// ============================================================================
// Kernel G (measured 24us): 32b x 64d NT GEMM, K=512, grid (32,8).
// QPROJ=true : g_q[b, y*64+d] = sum_k cur[b,k]            * B[(y*64+d)*512+k] + bias
// QPROJ=false: out[b, y*64+d] = sum_k g_c[b*4096+y*512+k] * B[(y*64+d)*512+k] + bias
// ============================================================================
__device__ __forceinline__ int swz(int cj, int row) { return 4 * (cj ^ ((row >> 1) & 7)); }

template<bool QPROJ>
__global__ void __launch_bounds__(256) k_gemm64(
    const float* __restrict__ Aext, const float* __restrict__ B,
    const float* __restrict__ bias, float* __restrict__ outext)
{
    __shared__ __align__(16) float Cs[2][32][32];   // 8 KB
    __shared__ __align__(16) float Ws[2][64][32];   // 16 KB
    const int tid = threadIdx.x;
    const int bB = blockIdx.x * 32;
    const int y  = blockIdx.y;
    const float* Bb = B + (long)y * 64 * 512;
    const int d0 = (tid >> 4) * 4;        // 0..60
    const int b0 = (tid & 15) * 2;        // 0..30

    const float* Abase = QPROJ ? Aext : (const float*)g_c;
    const long a_rstride = QPROJ ? 512 : 4096;
    const long a_yoff    = QPROJ ? 0   : (long)y * 512;

    u64 acc[2][4];
#pragma unroll
    for (int cb = 0; cb < 2; cb++)
#pragma unroll
        for (int dd = 0; dd < 4; dd++) acc[cb][dd] = 0ull;

    {
        int row = tid >> 3, cj = tid & 7;
        cp16(&Cs[0][row][swz(cj, row)],
             Abase + (long)(bB + row) * a_rstride + a_yoff + cj * 4);
    }
#pragma unroll
    for (int i = 0; i < 2; i++) {
        int idx = tid + 256 * i;
        int d = idx >> 3, cj = idx & 7;
        cp16(&Ws[0][d][swz(cj, d)], Bb + (long)d * 512 + cj * 4);
    }
    cp_commit();

    for (int kc = 0; kc < 16; kc++) {
        const int buf = kc & 1;
        if (kc + 1 < 16) {
            {
                int row = tid >> 3, cj = tid & 7;
                cp16(&Cs[buf ^ 1][row][swz(cj, row)],
                     Abase + (long)(bB + row) * a_rstride + a_yoff + (kc + 1) * 32 + cj * 4);
            }
#pragma unroll
            for (int i = 0; i < 2; i++) {
                int idx = tid + 256 * i;
                int d = idx >> 3, cj = idx & 7;
                cp16(&Ws[buf ^ 1][d][swz(cj, d)],
                     Bb + (long)d * 512 + (kc + 1) * 32 + cj * 4);
            }
        }
        cp_commit();
        cp_wait1();
        __syncthreads();

#pragma unroll
        for (int jg = 0; jg < 8; jg++) {
            ulonglong2 wv[4], cv[2];
#pragma unroll
            for (int dd = 0; dd < 4; dd++)
                wv[dd] = *(const ulonglong2*)&Ws[buf][d0 + dd][swz(jg, d0 + dd)];
#pragma unroll
            for (int cb = 0; cb < 2; cb++)
                cv[cb] = *(const ulonglong2*)&Cs[buf][b0 + cb][swz(jg, b0 + cb)];
#pragma unroll
            for (int cb = 0; cb < 2; cb++)
#pragma unroll
                for (int dd = 0; dd < 4; dd++) {
                    ffma2(acc[cb][dd], cv[cb].x, wv[dd].x);
                    ffma2(acc[cb][dd], cv[cb].y, wv[dd].y);
                }
        }
        __syncthreads();
    }

    float* Out = QPROJ ? (float*)g_q : outext;
    float4 bb = *(const float4*)&bias[y * 64 + d0];
#pragma unroll
    for (int cb = 0; cb < 2; cb++) {
        float v[4];
#pragma unroll
        for (int dd = 0; dd < 4; dd++) {
            float2 u = unpack2(acc[cb][dd]);
            v[dd] = u.x + u.y;
        }
        float4 o = make_float4(v[0] + bb.x, v[1] + bb.y, v[2] + bb.z, v[3] + bb.w);
        *(float4*)&Out[(long)(bB + b0 + cb) * 512 + y * 64 + d0] = o;
    }
}

// ============================================================================
// Kernel B: r[b,h,n] = sum_k q[b, h*64+k] * Wk[h*64+k, n]   (NN, K=64)
// ============================================================================
__global__ void __launch_bounds__(256) k_rproj(const float* __restrict__ Wk)
{
    __shared__ __align__(16) float Wks[64][128];
    __shared__ __align__(16) float qs[32][64];
    const int tid = threadIdx.x;
    const int nc = blockIdx.x;
    const int bB = blockIdx.y * 32;
    const int h  = blockIdx.z;

#pragma unroll
    for (int it = 0; it < 8; it++) {
        int idx = tid + 256 * it;
        int k = idx >> 5, n4 = (idx & 31) * 4;
        *(float4*)&Wks[k][n4] = *(const float4*)&Wk[(h * 64 + k) * 512 + nc * 128 + n4];
    }
#pragma unroll
    for (int it = 0; it < 2; it++) {
        int idx = tid + 256 * it;
        int bb = idx >> 4, k4 = (idx & 15) * 4;
        *(float4*)&qs[bb][k4] = *(const float4*)&g_q[(bB + bb) * 512 + h * 64 + k4];
    }
    __syncthreads();

    const int n0 = (tid & 31) * 4;
    const int b0 = (tid >> 5) * 4;
    u64 acc[4][2];
#pragma unroll
    for (int a = 0; a < 4; a++) { acc[a][0] = 0ull; acc[a][1] = 0ull; }

#pragma unroll
    for (int k = 0; k < 64; k++) {
        ulonglong2 w2 = *(const ulonglong2*)&Wks[k][n0];
#pragma unroll
        for (int cb = 0; cb < 4; cb++) {
            float x = qs[b0 + cb][k];
            u64 xx = pack2(x, x);
            ffma2(acc[cb][0], xx, w2.x);
            ffma2(acc[cb][1], xx, w2.y);
        }
    }
#pragma unroll
    for (int cb = 0; cb < 4; cb++) {
        float2 p0 = unpack2(acc[cb][0]), p1 = unpack2(acc[cb][1]);
        float4 o = make_float4(p0.x, p0.y, p1.x, p1.y);
        *(float4*)&g_r[((bB + b0 + cb) * 8 + h) * 512 + nc * 128 + n0] = o;
    }
}

// ============================================================================
// Kernel C: WARP-PER-HEAD streaming attention.
// 1 CTA / batch row, 8 warps = 8 heads. Lane l owns j in [16l, 16l+16).
// Per 2-timestep tile: load x slice into REGISTERS (read smem once, zero
// head replication), warp-butterfly score reduce, warp-local online softmax,
// accumulate from the same registers. One barrier per tile (buffer mgmt).
// ============================================================================
__device__ __forceinline__ void prefetch_tile2(
    float* dst, const float* __restrict__ prevb, const float* __restrict__ curb,
    int tile, int tid)
{
    int tr = tid >> 7;              // 0..1
    int c = (tid & 127) * 4;        // 0..508
    int gt = tile * TTILE + tr;
    const float* src = (gt < HIST) ? (prevb + (long)gt * 512 + c) : (curb + c);
    cp16(dst + tr * 512 + c, src);
}

__global__ void __launch_bounds__(256) k_attn(
    const float* __restrict__ cur, const float* __restrict__ prev,
    const float* __restrict__ mask, const float* __restrict__ bk)
{
    __shared__ __align__(16) float xb[NBUF][TTILE][DM];   // 24 KB
    __shared__ float mask_s[TT];

    const int tid = threadIdx.x;
    const int b = blockIdx.x;
    const int w = tid >> 5, lane = tid & 31;     // w = head

    const float* prevb = prev + (long)b * HIST * 512;
    const float* curb  = cur  + (long)b * 512;

    if (tid < TT) mask_s[tid] = mask[b * TT + tid];

    // sb = q[b, head w] · bk[head w]  (replicated to all lanes via butterfly)
    float sb;
    {
        float q1 = g_q[b * 512 + w * 64 + lane];
        float q2 = g_q[b * 512 + w * 64 + 32 + lane];
        float sv = q1 * bk[w * 64 + lane] + q2 * bk[w * 64 + 32 + lane];
#pragma unroll
        for (int o = 16; o; o >>= 1) sv += __shfl_xor_sync(0xffffffffu, sv, o);
        sb = sv;
    }

    // rf: r[b, head w, 16l .. 16l+16)
    u64 rf[8];
    {
        const float* rp = &g_r[(long)b * 4096 + w * 512 + lane * 16];
#pragma unroll
        for (int c = 0; c < 4; c++) {
            ulonglong2 v = *(const ulonglong2*)(rp + 4 * c);
            rf[2 * c + 0] = v.x;
            rf[2 * c + 1] = v.y;
        }
    }
    u64 acc[8];
#pragma unroll
    for (int i = 0; i < 8; i++) acc[i] = 0ull;
    float m = -CUDART_INF_F, l = 0.f;

    // prime 5 tiles
#pragma unroll
    for (int i = 0; i < 5; i++) {
        prefetch_tile2(&xb[i][0][0], prevb, curb, i, tid);
        cp_commit();
    }
    __syncthreads();                       // mask_s visible

    for (int tile = 0; tile < NTILES; tile++) {
        const int buf = tile % NBUF;
        cp_wait4();                        // tile's group complete
        __syncthreads();                   // all warps done reading buf(tile-1)

        // ---- load x into registers (the ONLY smem read of this data) ----
        u64 x0[8], x1[8];
        {
            const float* xr = &xb[buf][0][lane * 16];
#pragma unroll
            for (int c = 0; c < 4; c++) {
                ulonglong2 v = *(const ulonglong2*)(xr + 4 * c);
                x0[2 * c] = v.x; x0[2 * c + 1] = v.y;
            }
            const float* xr1 = xr + DM;
#pragma unroll
            for (int c = 0; c < 4; c++) {
                ulonglong2 v = *(const ulonglong2*)(xr1 + 4 * c);
                x1[2 * c] = v.x; x1[2 * c + 1] = v.y;
            }
        }

        // keep 5 tiles in flight (buffer (tile+5)%6 == (tile-1)%6, safe:
        // every warp passed the barrier above, i.e. finished tile-1's reads)
        if (tile + 5 < NTILES)
            prefetch_tile2(&xb[(tile + 5) % NBUF][0][0], prevb, curb, tile + 5, tid);
        cp_commit();                       // uniform group count

        // ---- scores (warp-butterfly full reduce; all lanes get the sum) ----
        float sc0, sc1;
        {
            u64 sa = 0ull, sbb = 0ull;
#pragma unroll
            for (int i = 0; i < 8; i += 2) { ffma2(sa, rf[i], x0[i]); ffma2(sbb, rf[i+1], x0[i+1]); }
            float2 fa = unpack2(sa), fb = unpack2(sbb);
            float s = (fa.x + fa.y) + (fb.x + fb.y);
#pragma unroll
            for (int o = 16; o; o >>= 1) s += __shfl_xor_sync(0xffffffffu, s, o);
            sc0 = s;
        }
        {
            u64 sa = 0ull, sbb = 0ull;
#pragma unroll
            for (int i = 0; i < 8; i += 2) { ffma2(sa, rf[i], x1[i]); ffma2(sbb, rf[i+1], x1[i+1]); }
            float2 fa = unpack2(sa), fb = unpack2(sbb);
            float s = (fa.x + fa.y) + (fb.x + fb.y);
#pragma unroll
            for (int o = 16; o; o >>= 1) s += __shfl_xor_sync(0xffffffffu, s, o);
            sc1 = s;
        }

        // ---- warp-local online softmax (uniform branch within warp) ----
        float lg0 = (sc0 + sb) * 0.125f + mask_s[tile * TTILE + 0];
        float lg1 = (sc1 + sb) * 0.125f + mask_s[tile * TTILE + 1];
        float mx = fmaxf(lg0, lg1);
        if (mx > m) {
            float scl = __expf(m - mx);    // first tile: exp(-inf)=0
            u64 sclp = pack2(scl, scl);
#pragma unroll
            for (int i = 0; i < 8; i++) fmul2(acc[i], sclp);
            l *= scl;
            m = mx;
        }
        float p0 = __expf(lg0 - m);
        float p1 = __expf(lg1 - m);
        l += p0 + p1;

        // ---- accumulate from registers (no 2nd smem pass) ----
        u64 pv0 = pack2(p0, p0), pv1 = pack2(p1, p1);
#pragma unroll
        for (int i = 0; i < 8; i++) ffma2(acc[i], pv0, x0[i]);
#pragma unroll
        for (int i = 0; i < 8; i++) ffma2(acc[i], pv1, x1[i]);
    }

    float inv = 1.0f / l;
    float* cpo = &g_c[(long)b * 4096 + w * 512 + lane * 16];
#pragma unroll
    for (int c = 0; c < 4; c++) {
        float2 v0 = unpack2(acc[2 * c + 0]);
        float2 v1 = unpack2(acc[2 * c + 1]);
        float4 o = make_float4(v0.x * inv, v0.y * inv, v1.x * inv, v1.y * inv);
        *(float4*)(cpo + 4 * c) = o;
    }
}

// ============================================================================
extern "C" void kernel_launch(void* const* d_in, const int* in_sizes, int n_in,
                              void* d_out, int out_size)
{
    const float* cur  = (const float*)d_in[0];   // [1024, 512]
    const float* prev = (const float*)d_in[1];   // [1024, 199, 512]
    const float* mask = (const float*)d_in[2];   // [1024, 200]
    const float* Wq   = (const float*)d_in[3];   // [512, 512]
    const float* bq   = (const float*)d_in[4];   // [512]
    const float* Wk   = (const float*)d_in[5];   // [512, 512]
    const float* bk   = (const float*)d_in[6];   // [512]
    const float* Wv   = (const float*)d_in[7];   // [512, 512]
    const float* bv   = (const float*)d_in[8];   // [512]
    float* out = (float*)d_out;                  // [1024, 512]

    // q = cur @ Wq^T + bq          (writes g_q internally)
    k_gemm64<true ><<<dim3(32, 8), 256>>>(cur, Wq, bq, nullptr);
    // r[b,h,:] = Wk_h^T q_h        (g_q -> g_r)
    k_rproj<<<dim3(4, 32, 8), 256>>>(Wk);
    // warp-per-head streaming attention (-> g_c)
    k_attn <<<dim3(1024), 256>>>(cur, prev, mask, bk);
    // out = c @ Wv_h^T + bv        (reads g_c internally)
    k_gemm64<false><<<dim3(32, 8), 256>>>(nullptr, Wv, bv, out);
}

// round 12
// speedup vs baseline: 1.4708x; 1.4708x over previous
#include <cuda_runtime.h>
#include <math_constants.h>

#define BS   1024
#define DM   512
#define NH   8
#define DK   64
#define HIST 199
#define TT   200
#define TTILE 8
#define NBUF 3
#define TSPLIT 4
#define T_PER_SPLIT 50
#define NT_SPLIT 7             // ceil(50/8)

// Scratch — referenced ONLY inside device code (host-side use passes the host
// shadow address; ATS makes it silently dereferenceable -> garbage).
__device__ float g_q[BS * DM];                     // 2 MB
__device__ float g_r[BS * NH * DM];                // 16 MB
__device__ float g_c[BS * NH * DM];                // 16 MB
__device__ float g_pc[BS * TSPLIT * NH * DM];      // 64 MB  unnormalized partial c
__device__ float g_pml[BS * TSPLIT * 16];          // 256 KB m[8], l[8] per (b,s)

typedef unsigned long long u64;

// ---- packed f32x2 helpers --------------------------------------------------
__device__ __forceinline__ u64 pack2(float x, float y) {
    u64 r; asm("mov.b64 %0, {%1, %2};" : "=l"(r) : "f"(x), "f"(y)); return r;
}
__device__ __forceinline__ float2 unpack2(u64 v) {
    float2 d; asm("mov.b64 {%0, %1}, %2;" : "=f"(d.x), "=f"(d.y) : "l"(v)); return d;
}
__device__ __forceinline__ void ffma2(u64& acc, u64 a, u64 b) {
    asm("fma.rn.f32x2 %0, %1, %2, %0;" : "+l"(acc) : "l"(a), "l"(b));
}
__device__ __forceinline__ void fmul2(u64& a, u64 b) {
    asm("mul.rn.f32x2 %0, %0, %1;" : "+l"(a) : "l"(b));
}
__device__ __forceinline__ void cp16(void* smem_dst, const void* gsrc) {
    unsigned s = (unsigned)__cvta_generic_to_shared(smem_dst);
    asm volatile("cp.async.cg.shared.global [%0], [%1], 16;" :: "r"(s), "l"(gsrc));
}
__device__ __forceinline__ void cp_commit() { asm volatile("cp.async.commit_group;" ::: "memory"); }
__device__ __forceinline__ void cp_wait1()  { asm volatile("cp.async.wait_group 1;" ::: "memory"); }

// ============================================================================
// Kernel G (measured 24us): 32b x 64d NT GEMM, K=512, grid (32,8).
// QPROJ=true : g_q[b, y*64+d] = sum_k cur[b,k]            * B[(y*64+d)*512+k] + bias
// QPROJ=false: out[b, y*64+d] = sum_k g_c[b*4096+y*512+k] * B[(y*64+d)*512+k] + bias
// ============================================================================
__device__ __forceinline__ int swz(int cj, int row) { return 4 * (cj ^ ((row >> 1) & 7)); }

template<bool QPROJ>
__global__ void __launch_bounds__(256) k_gemm64(
    const float* __restrict__ Aext, const float* __restrict__ B,
    const float* __restrict__ bias, float* __restrict__ outext)
{
    __shared__ __align__(16) float Cs[2][32][32];   // 8 KB
    __shared__ __align__(16) float Ws[2][64][32];   // 16 KB
    const int tid = threadIdx.x;
    const int bB = blockIdx.x * 32;
    const int y  = blockIdx.y;
    const float* Bb = B + (long)y * 64 * 512;
    const int d0 = (tid >> 4) * 4;        // 0..60
    const int b0 = (tid & 15) * 2;        // 0..30

    const float* Abase = QPROJ ? Aext : (const float*)g_c;
    const long a_rstride = QPROJ ? 512 : 4096;
    const long a_yoff    = QPROJ ? 0   : (long)y * 512;

    u64 acc[2][4];
#pragma unroll
    for (int cb = 0; cb < 2; cb++)
#pragma unroll
        for (int dd = 0; dd < 4; dd++) acc[cb][dd] = 0ull;

    {
        int row = tid >> 3, cj = tid & 7;
        cp16(&Cs[0][row][swz(cj, row)],
             Abase + (long)(bB + row) * a_rstride + a_yoff + cj * 4);
    }
#pragma unroll
    for (int i = 0; i < 2; i++) {
        int idx = tid + 256 * i;
        int d = idx >> 3, cj = idx & 7;
        cp16(&Ws[0][d][swz(cj, d)], Bb + (long)d * 512 + cj * 4);
    }
    cp_commit();

    for (int kc = 0; kc < 16; kc++) {
        const int buf = kc & 1;
        if (kc + 1 < 16) {
            {
                int row = tid >> 3, cj = tid & 7;
                cp16(&Cs[buf ^ 1][row][swz(cj, row)],
                     Abase + (long)(bB + row) * a_rstride + a_yoff + (kc + 1) * 32 + cj * 4);
            }
#pragma unroll
            for (int i = 0; i < 2; i++) {
                int idx = tid + 256 * i;
                int d = idx >> 3, cj = idx & 7;
                cp16(&Ws[buf ^ 1][d][swz(cj, d)],
                     Bb + (long)d * 512 + (kc + 1) * 32 + cj * 4);
            }
        }
        cp_commit();
        cp_wait1();
        __syncthreads();

#pragma unroll
        for (int jg = 0; jg < 8; jg++) {
            ulonglong2 wv[4], cv[2];
#pragma unroll
            for (int dd = 0; dd < 4; dd++)
                wv[dd] = *(const ulonglong2*)&Ws[buf][d0 + dd][swz(jg, d0 + dd)];
#pragma unroll
            for (int cb = 0; cb < 2; cb++)
                cv[cb] = *(const ulonglong2*)&Cs[buf][b0 + cb][swz(jg, b0 + cb)];
#pragma unroll
            for (int cb = 0; cb < 2; cb++)
#pragma unroll
                for (int dd = 0; dd < 4; dd++) {
                    ffma2(acc[cb][dd], cv[cb].x, wv[dd].x);
                    ffma2(acc[cb][dd], cv[cb].y, wv[dd].y);
                }
        }
        __syncthreads();
    }

    float* Out = QPROJ ? (float*)g_q : outext;
    float4 bb = *(const float4*)&bias[y * 64 + d0];
#pragma unroll
    for (int cb = 0; cb < 2; cb++) {
        float v[4];
#pragma unroll
        for (int dd = 0; dd < 4; dd++) {
            float2 u = unpack2(acc[cb][dd]);
            v[dd] = u.x + u.y;
        }
        float4 o = make_float4(v[0] + bb.x, v[1] + bb.y, v[2] + bb.z, v[3] + bb.w);
        *(float4*)&Out[(long)(bB + b0 + cb) * 512 + y * 64 + d0] = o;
    }
}

// ============================================================================
// Kernel B: r[b,h,n] = sum_k q[b, h*64+k] * Wk[h*64+k, n]   (NN, K=64)
// ============================================================================
__global__ void __launch_bounds__(256) k_rproj(const float* __restrict__ Wk)
{
    __shared__ __align__(16) float Wks[64][128];
    __shared__ __align__(16) float qs[32][64];
    const int tid = threadIdx.x;
    const int nc = blockIdx.x;
    const int bB = blockIdx.y * 32;
    const int h  = blockIdx.z;

#pragma unroll
    for (int it = 0; it < 8; it++) {
        int idx = tid + 256 * it;
        int k = idx >> 5, n4 = (idx & 31) * 4;
        *(float4*)&Wks[k][n4] = *(const float4*)&Wk[(h * 64 + k) * 512 + nc * 128 + n4];
    }
#pragma unroll
    for (int it = 0; it < 2; it++) {
        int idx = tid + 256 * it;
        int bb = idx >> 4, k4 = (idx & 15) * 4;
        *(float4*)&qs[bb][k4] = *(const float4*)&g_q[(bB + bb) * 512 + h * 64 + k4];
    }
    __syncthreads();

    const int n0 = (tid & 31) * 4;
    const int b0 = (tid >> 5) * 4;
    u64 acc[4][2];
#pragma unroll
    for (int a = 0; a < 4; a++) { acc[a][0] = 0ull; acc[a][1] = 0ull; }

#pragma unroll
    for (int k = 0; k < 64; k++) {
        ulonglong2 w2 = *(const ulonglong2*)&Wks[k][n0];
#pragma unroll
        for (int cb = 0; cb < 4; cb++) {
            float x = qs[b0 + cb][k];
            u64 xx = pack2(x, x);
            ffma2(acc[cb][0], xx, w2.x);
            ffma2(acc[cb][1], xx, w2.y);
        }
    }
#pragma unroll
    for (int cb = 0; cb < 4; cb++) {
        float2 p0 = unpack2(acc[cb][0]), p1 = unpack2(acc[cb][1]);
        float4 o = make_float4(p0.x, p0.y, p1.x, p1.y);
        *(float4*)&g_r[((bB + b0 + cb) * 8 + h) * 512 + nc * 128 + n0] = o;
    }
}

// ============================================================================
// Kernel C: SPLIT-T streaming attention, R9 mapping, TTILE=8 (16KB tiles).
// grid (1024, 4): CTA (b,s) handles timesteps [s*50, s*50+50), 7 tiles of 8.
// Warp w owns j-slice [w*64, w*64+64); lane (h=l>>2, g=l&3) owns the four
// float4 chunks w*64 + g*4 + 16c (broadcast across the 8 h-lanes -> 1 wf).
// Writes UNNORMALIZED partial acc to g_pc and (m, l) to g_pml.
// ============================================================================
__device__ __forceinline__ void prefetch_tile_s(
    float* dst, const float* __restrict__ prevb, const float* __restrict__ curb,
    int s, int tile, int tid)
{
#pragma unroll
    for (int i = 0; i < 4; i++) {
        int idx = tid + 256 * i;        // 1024 float4 = 8 rows x 512 floats
        int tr = idx >> 7;
        int c = (idx & 127) * 4;
        int lt = tile * TTILE + tr;     // 0..55
        if (lt > T_PER_SPLIT - 1) lt = T_PER_SPLIT - 1;   // clamp (masked -inf)
        int gt = s * T_PER_SPLIT + lt;  // <= 199
        const float* src = (gt < HIST) ? (prevb + (long)gt * 512 + c) : (curb + c);
        cp16(dst + tr * 512 + c, src);
    }
}

__global__ void __launch_bounds__(256) k_attn(
    const float* __restrict__ cur, const float* __restrict__ prev,
    const float* __restrict__ mask, const float* __restrict__ bk)
{
    __shared__ __align__(16) float xb[NBUF][TTILE][DM];   // 48 KB
    __shared__ __align__(16) float s_part[8][8][TTILE];   // 2 KB
    __shared__ float mask_s[NT_SPLIT * TTILE];            // 56
    __shared__ float sb_s[8];

    const int tid = threadIdx.x;
    const int b = blockIdx.x;
    const int s = blockIdx.y;
    const int w = tid >> 5, lane = tid & 31;
    const int h = lane >> 2, g = lane & 3;

    const float* prevb = prev + (long)b * HIST * 512;
    const float* curb  = cur  + (long)b * 512;

    if (tid < NT_SPLIT * TTILE)
        mask_s[tid] = (tid < T_PER_SPLIT)
            ? mask[b * TT + s * T_PER_SPLIT + tid] : -CUDART_INF_F;
    {   // sb[h] = q[b,h,:]·bk[h,:]; warp w handles head w
        float q1 = g_q[b * 512 + w * 64 + lane];
        float q2 = g_q[b * 512 + w * 64 + 32 + lane];
        float sv = q1 * bk[w * 64 + lane] + q2 * bk[w * 64 + 32 + lane];
#pragma unroll
        for (int o = 16; o; o >>= 1) sv += __shfl_xor_sync(0xffffffffu, sv, o);
        if (lane == 0) sb_s[w] = sv;
    }

    // r fragment: 4 strided float4 chunks (matches x-access mapping)
    u64 rf[8];
    {
        const float* rp = &g_r[(long)b * 4096 + h * 512 + w * 64 + g * 4];
#pragma unroll
        for (int c = 0; c < 4; c++) {
            ulonglong2 v = *(const ulonglong2*)(rp + 16 * c);
            rf[2 * c + 0] = v.x;
            rf[2 * c + 1] = v.y;
        }
    }
    u64 acc[8];
#pragma unroll
    for (int i = 0; i < 8; i++) acc[i] = 0ull;
    float m = -CUDART_INF_F, l = 0.f;

    // prime 2 tiles (2 groups in flight)
#pragma unroll
    for (int i = 0; i < 2; i++) {
        prefetch_tile_s(&xb[i][0][0], prevb, curb, s, i, tid);
        cp_commit();
    }
    __syncthreads();                       // sb_s / mask_s visible
    const float sb = sb_s[h];

    for (int tile = 0; tile < NT_SPLIT; tile++) {
        const int buf = tile % NBUF;
        cp_wait1();                        // tile's group complete (1 newer pend)
        __syncthreads();

        const float* xbase = &xb[buf][0][w * 64 + g * 4];
        // ---- partial scores (8 independent t-chains) ----
#pragma unroll
        for (int t = 0; t < TTILE; t++) {
            const float* xr = xbase + t * DM;
            ulonglong2 x0 = *(const ulonglong2*)(xr);
            ulonglong2 x1 = *(const ulonglong2*)(xr + 16);
            ulonglong2 x2 = *(const ulonglong2*)(xr + 32);
            ulonglong2 x3 = *(const ulonglong2*)(xr + 48);
            u64 sa = 0ull, sc = 0ull;
            ffma2(sa, rf[0], x0.x); ffma2(sc, rf[1], x0.y);
            ffma2(sa, rf[2], x1.x); ffma2(sc, rf[3], x1.y);
            ffma2(sa, rf[4], x2.x); ffma2(sc, rf[5], x2.y);
            ffma2(sa, rf[6], x3.x); ffma2(sc, rf[7], x3.y);
            float2 fa = unpack2(sa), fc = unpack2(sc);
            float sv = (fa.x + fa.y) + (fc.x + fc.y);
            sv += __shfl_xor_sync(0xffffffffu, sv, 1);
            sv += __shfl_xor_sync(0xffffffffu, sv, 2);
            if (g == 0) s_part[w][h][t] = sv;
        }
        __syncthreads();                   // s_part complete

        // keep 2 tiles in flight; buffer (tile+2)%3 == (tile-1)%3, safe:
        // acc(tile-1) precedes this iteration's first barrier for every warp.
        if (tile + 2 < NT_SPLIT)
            prefetch_tile_s(&xb[(tile + 2) % NBUF][0][0], prevb, curb, s, tile + 2, tid);
        cp_commit();                       // uniform group count

        // ---- per-lane replicated online softmax for head h ----
        float4 a0 = make_float4(0.f, 0.f, 0.f, 0.f);
        float4 a1 = make_float4(0.f, 0.f, 0.f, 0.f);
#pragma unroll
        for (int w2 = 0; w2 < 8; w2++) {
            float4 v0 = *(const float4*)&s_part[w2][h][0];
            float4 v1 = *(const float4*)&s_part[w2][h][4];
            a0.x += v0.x; a0.y += v0.y; a0.z += v0.z; a0.w += v0.w;
            a1.x += v1.x; a1.y += v1.y; a1.z += v1.z; a1.w += v1.w;
        }
        const float* mk = &mask_s[tile * TTILE];
        float lg[TTILE];
        lg[0] = (a0.x + sb) * 0.125f + mk[0];
        lg[1] = (a0.y + sb) * 0.125f + mk[1];
        lg[2] = (a0.z + sb) * 0.125f + mk[2];
        lg[3] = (a0.w + sb) * 0.125f + mk[3];
        lg[4] = (a1.x + sb) * 0.125f + mk[4];
        lg[5] = (a1.y + sb) * 0.125f + mk[5];
        lg[6] = (a1.z + sb) * 0.125f + mk[6];
        lg[7] = (a1.w + sb) * 0.125f + mk[7];
        float mx = lg[0];
#pragma unroll
        for (int t = 1; t < TTILE; t++) mx = fmaxf(mx, lg[t]);
        float m_new = fmaxf(m, mx);
        float p[TTILE], ps = 0.f;
#pragma unroll
        for (int t = 0; t < TTILE; t++) { p[t] = __expf(lg[t] - m_new); ps += p[t]; }
        float scl = __expf(m - m_new);
        l = l * scl + ps;
        m = m_new;

        // ---- rescale + accumulate weighted x ----
        u64 sclp = pack2(scl, scl);
#pragma unroll
        for (int i = 0; i < 8; i++) fmul2(acc[i], sclp);
#pragma unroll
        for (int t = 0; t < TTILE; t++) {
            const float* xr = xbase + t * DM;
            ulonglong2 x0 = *(const ulonglong2*)(xr);
            ulonglong2 x1 = *(const ulonglong2*)(xr + 16);
            ulonglong2 x2 = *(const ulonglong2*)(xr + 32);
            ulonglong2 x3 = *(const ulonglong2*)(xr + 48);
            u64 pv = pack2(p[t], p[t]);
            ffma2(acc[0], pv, x0.x); ffma2(acc[1], pv, x0.y);
            ffma2(acc[2], pv, x1.x); ffma2(acc[3], pv, x1.y);
            ffma2(acc[4], pv, x2.x); ffma2(acc[5], pv, x2.y);
            ffma2(acc[6], pv, x3.x); ffma2(acc[7], pv, x3.y);
        }
    }

    // ---- write UNNORMALIZED partial + (m, l) ----
    float* cpo = &g_pc[((long)(b * TSPLIT + s) * 8 + h) * 512 + w * 64 + g * 4];
#pragma unroll
    for (int c = 0; c < 4; c++) {
        float2 v0 = unpack2(acc[2 * c + 0]);
        float2 v1 = unpack2(acc[2 * c + 1]);
        float4 o = make_float4(v0.x, v0.y, v1.x, v1.y);
        *(float4*)(cpo + 16 * c) = o;
    }
    if (w == 0 && g == 0) {                 // lanes h=0..7, one per head
        g_pml[(b * TSPLIT + s) * 16 + h]     = m;
        g_pml[(b * TSPLIT + s) * 16 + 8 + h] = l;
    }
}

// ============================================================================
// Kernel M: merge 4 split partials -> g_c.  grid 1024, block 256.
// ============================================================================
__global__ void __launch_bounds__(256) k_merge()
{
    __shared__ float wol[TSPLIT][8];
    const int tid = threadIdx.x;
    const int b = blockIdx.x;

    if (tid < 32) {
        int s = tid >> 3, h = tid & 7;
        float m = g_pml[(b * TSPLIT + s) * 16 + h];
        float l = g_pml[(b * TSPLIT + s) * 16 + 8 + h];
        float M = m;
        M = fmaxf(M, __shfl_xor_sync(0xffffffffu, M, 8));
        M = fmaxf(M, __shfl_xor_sync(0xffffffffu, M, 16));
        float wgt = __expf(m - M);
        float wl = wgt * l;
        wl += __shfl_xor_sync(0xffffffffu, wl, 8);
        wl += __shfl_xor_sync(0xffffffffu, wl, 16);
        wol[s][h] = wgt / wl;
    }
    __syncthreads();

#pragma unroll
    for (int c = 0; c < 4; c++) {
        int j = c * 1024 + tid * 4;
        int h = j >> 9;
        float4 a = make_float4(0.f, 0.f, 0.f, 0.f);
#pragma unroll
        for (int s = 0; s < TSPLIT; s++) {
            float4 v = *(const float4*)&g_pc[((long)(b * TSPLIT + s)) * 4096 + j];
            float wv = wol[s][h];
            a.x += wv * v.x; a.y += wv * v.y;
            a.z += wv * v.z; a.w += wv * v.w;
        }
        *(float4*)&g_c[(long)b * 4096 + j] = a;
    }
}

// ============================================================================
extern "C" void kernel_launch(void* const* d_in, const int* in_sizes, int n_in,
                              void* d_out, int out_size)
{
    const float* cur  = (const float*)d_in[0];   // [1024, 512]
    const float* prev = (const float*)d_in[1];   // [1024, 199, 512]
    const float* mask = (const float*)d_in[2];   // [1024, 200]
    const float* Wq   = (const float*)d_in[3];   // [512, 512]
    const float* bq   = (const float*)d_in[4];   // [512]
    const float* Wk   = (const float*)d_in[5];   // [512, 512]
    const float* bk   = (const float*)d_in[6];   // [512]
    const float* Wv   = (const float*)d_in[7];   // [512, 512]
    const float* bv   = (const float*)d_in[8];   // [512]
    float* out = (float*)d_out;                  // [1024, 512]

    // q = cur @ Wq^T + bq          (writes g_q internally)
    k_gemm64<true ><<<dim3(32, 8), 256>>>(cur, Wq, bq, nullptr);
    // r[b,h,:] = Wk_h^T q_h        (g_q -> g_r)
    k_rproj<<<dim3(4, 32, 8), 256>>>(Wk);
    // split-T streaming attention  (-> g_pc, g_pml)
    k_attn <<<dim3(1024, TSPLIT), 256>>>(cur, prev, mask, bk);
    // merge partials               (-> g_c)
    k_merge<<<1024, 256>>>();
    // out = c @ Wv_h^T + bv        (reads g_c internally)
    k_gemm64<false><<<dim3(32, 8), 256>>>(nullptr, Wv, bv, out);
}

// round 13
// speedup vs baseline: 1.6316x; 1.1093x over previous
#include <cuda_runtime.h>
#include <math_constants.h>

#define BS   1024
#define DM   512
#define NH   8
#define DK   64
#define HIST 199
#define TT   200
#define TTILE 4
#define NBUF 5
#define TSPLIT 4
#define T_PER_SPLIT 50
#define NT_SPLIT 13            // ceil(50/4)

// Scratch — referenced ONLY inside device code (host-side use passes the host
// shadow address; ATS makes it silently dereferenceable -> garbage).
__device__ float g_q[BS * DM];                     // 2 MB
__device__ float g_r[BS * NH * DM];                // 16 MB
__device__ float g_c[BS * NH * DM];                // 16 MB
__device__ float g_pc[BS * TSPLIT * NH * DM];      // 64 MB  unnormalized partial c
__device__ float g_pml[BS * TSPLIT * 16];          // 256 KB m[8], l[8] per (b,s)

typedef unsigned long long u64;

// ---- packed f32x2 helpers --------------------------------------------------
__device__ __forceinline__ u64 pack2(float x, float y) {
    u64 r; asm("mov.b64 %0, {%1, %2};" : "=l"(r) : "f"(x), "f"(y)); return r;
}
__device__ __forceinline__ float2 unpack2(u64 v) {
    float2 d; asm("mov.b64 {%0, %1}, %2;" : "=f"(d.x), "=f"(d.y) : "l"(v)); return d;
}
__device__ __forceinline__ void ffma2(u64& acc, u64 a, u64 b) {
    asm("fma.rn.f32x2 %0, %1, %2, %0;" : "+l"(acc) : "l"(a), "l"(b));
}
__device__ __forceinline__ void fmul2(u64& a, u64 b) {
    asm("mul.rn.f32x2 %0, %0, %1;" : "+l"(a) : "l"(b));
}
__device__ __forceinline__ void cp16(void* smem_dst, const void* gsrc) {
    unsigned s = (unsigned)__cvta_generic_to_shared(smem_dst);
    asm volatile("cp.async.cg.shared.global [%0], [%1], 16;" :: "r"(s), "l"(gsrc));
}
__device__ __forceinline__ void cp_commit() { asm volatile("cp.async.commit_group;" ::: "memory"); }
__device__ __forceinline__ void cp_wait2()  { asm volatile("cp.async.wait_group 2;" ::: "memory"); }
__device__ __forceinline__ void cp_wait1()  { asm volatile("cp.async.wait_group 1;" ::: "memory"); }

// ============================================================================
// Kernel G (measured 24us): 32b x 64d NT GEMM, K=512, grid (32,8).
// QPROJ=true : g_q[b, y*64+d] = sum_k cur[b,k]            * B[(y*64+d)*512+k] + bias
// QPROJ=false: out[b, y*64+d] = sum_k g_c[b*4096+y*512+k] * B[(y*64+d)*512+k] + bias
// ============================================================================
__device__ __forceinline__ int swz(int cj, int row) { return 4 * (cj ^ ((row >> 1) & 7)); }

template<bool QPROJ>
__global__ void __launch_bounds__(256) k_gemm64(
    const float* __restrict__ Aext, const float* __restrict__ B,
    const float* __restrict__ bias, float* __restrict__ outext)
{
    __shared__ __align__(16) float Cs[2][32][32];   // 8 KB
    __shared__ __align__(16) float Ws[2][64][32];   // 16 KB
    const int tid = threadIdx.x;
    const int bB = blockIdx.x * 32;
    const int y  = blockIdx.y;
    const float* Bb = B + (long)y * 64 * 512;
    const int d0 = (tid >> 4) * 4;        // 0..60
    const int b0 = (tid & 15) * 2;        // 0..30

    const float* Abase = QPROJ ? Aext : (const float*)g_c;
    const long a_rstride = QPROJ ? 512 : 4096;
    const long a_yoff    = QPROJ ? 0   : (long)y * 512;

    u64 acc[2][4];
#pragma unroll
    for (int cb = 0; cb < 2; cb++)
#pragma unroll
        for (int dd = 0; dd < 4; dd++) acc[cb][dd] = 0ull;

    {
        int row = tid >> 3, cj = tid & 7;
        cp16(&Cs[0][row][swz(cj, row)],
             Abase + (long)(bB + row) * a_rstride + a_yoff + cj * 4);
    }
#pragma unroll
    for (int i = 0; i < 2; i++) {
        int idx = tid + 256 * i;
        int d = idx >> 3, cj = idx & 7;
        cp16(&Ws[0][d][swz(cj, d)], Bb + (long)d * 512 + cj * 4);
    }
    cp_commit();

    for (int kc = 0; kc < 16; kc++) {
        const int buf = kc & 1;
        if (kc + 1 < 16) {
            {
                int row = tid >> 3, cj = tid & 7;
                cp16(&Cs[buf ^ 1][row][swz(cj, row)],
                     Abase + (long)(bB + row) * a_rstride + a_yoff + (kc + 1) * 32 + cj * 4);
            }
#pragma unroll
            for (int i = 0; i < 2; i++) {
                int idx = tid + 256 * i;
                int d = idx >> 3, cj = idx & 7;
                cp16(&Ws[buf ^ 1][d][swz(cj, d)],
                     Bb + (long)d * 512 + (kc + 1) * 32 + cj * 4);
            }
        }
        cp_commit();
        cp_wait1();
        __syncthreads();

#pragma unroll
        for (int jg = 0; jg < 8; jg++) {
            ulonglong2 wv[4], cv[2];
#pragma unroll
            for (int dd = 0; dd < 4; dd++)
                wv[dd] = *(const ulonglong2*)&Ws[buf][d0 + dd][swz(jg, d0 + dd)];
#pragma unroll
            for (int cb = 0; cb < 2; cb++)
                cv[cb] = *(const ulonglong2*)&Cs[buf][b0 + cb][swz(jg, b0 + cb)];
#pragma unroll
            for (int cb = 0; cb < 2; cb++)
#pragma unroll
                for (int dd = 0; dd < 4; dd++) {
                    ffma2(acc[cb][dd], cv[cb].x, wv[dd].x);
                    ffma2(acc[cb][dd], cv[cb].y, wv[dd].y);
                }
        }
        __syncthreads();
    }

    float* Out = QPROJ ? (float*)g_q : outext;
    float4 bb = *(const float4*)&bias[y * 64 + d0];
#pragma unroll
    for (int cb = 0; cb < 2; cb++) {
        float v[4];
#pragma unroll
        for (int dd = 0; dd < 4; dd++) {
            float2 u = unpack2(acc[cb][dd]);
            v[dd] = u.x + u.y;
        }
        float4 o = make_float4(v[0] + bb.x, v[1] + bb.y, v[2] + bb.z, v[3] + bb.w);
        *(float4*)&Out[(long)(bB + b0 + cb) * 512 + y * 64 + d0] = o;
    }
}

// ============================================================================
// Kernel B: r[b,h,n] = sum_k q[b, h*64+k] * Wk[h*64+k, n]   (NN, K=64)
// ============================================================================
__global__ void __launch_bounds__(256) k_rproj(const float* __restrict__ Wk)
{
    __shared__ __align__(16) float Wks[64][128];
    __shared__ __align__(16) float qs[32][64];
    const int tid = threadIdx.x;
    const int nc = blockIdx.x;
    const int bB = blockIdx.y * 32;
    const int h  = blockIdx.z;

#pragma unroll
    for (int it = 0; it < 8; it++) {
        int idx = tid + 256 * it;
        int k = idx >> 5, n4 = (idx & 31) * 4;
        *(float4*)&Wks[k][n4] = *(const float4*)&Wk[(h * 64 + k) * 512 + nc * 128 + n4];
    }
#pragma unroll
    for (int it = 0; it < 2; it++) {
        int idx = tid + 256 * it;
        int bb = idx >> 4, k4 = (idx & 15) * 4;
        *(float4*)&qs[bb][k4] = *(const float4*)&g_q[(bB + bb) * 512 + h * 64 + k4];
    }
    __syncthreads();

    const int n0 = (tid & 31) * 4;
    const int b0 = (tid >> 5) * 4;
    u64 acc[4][2];
#pragma unroll
    for (int a = 0; a < 4; a++) { acc[a][0] = 0ull; acc[a][1] = 0ull; }

#pragma unroll
    for (int k = 0; k < 64; k++) {
        ulonglong2 w2 = *(const ulonglong2*)&Wks[k][n0];
#pragma unroll
        for (int cb = 0; cb < 4; cb++) {
            float x = qs[b0 + cb][k];
            u64 xx = pack2(x, x);
            ffma2(acc[cb][0], xx, w2.x);
            ffma2(acc[cb][1], xx, w2.y);
        }
    }
#pragma unroll
    for (int cb = 0; cb < 4; cb++) {
        float2 p0 = unpack2(acc[cb][0]), p1 = unpack2(acc[cb][1]);
        float4 o = make_float4(p0.x, p0.y, p1.x, p1.y);
        *(float4*)&g_r[((bB + b0 + cb) * 8 + h) * 512 + nc * 128 + n0] = o;
    }
}

// ============================================================================
// Kernel C: SPLIT-T attention, SOFTWARE-PIPELINED softmax (1 tile behind).
// grid (1024, 4): CTA (b,s) handles timesteps [s*50, s*50+50), 13 tiles of 4.
// Iter i: wait -> ONE bar -> prefetch(i+3) -> scores(i)->s_part[i&1]
//         -> softmax+acc(i-1) from s_part[(i-1)&1].  Epilogue iter drains.
// Buffer safety: xb NBUF=5, lead 3; any buffer's writer is >=1 barrier after
// its last reader (acc(i-1) in iter i; earliest rewrite of that buf is the
// prefetch in iter i+1, post-bar(i+1)). Same argument for s_part (2 bufs).
// ============================================================================
__device__ __forceinline__ void prefetch_tile_s(
    float* dst, const float* __restrict__ prevb, const float* __restrict__ curb,
    int s, int tile, int tid)
{
#pragma unroll
    for (int i = 0; i < 2; i++) {
        int idx = tid + 256 * i;        // 512 float4 = 4 rows x 512 floats
        int tr = idx >> 7;
        int c = (idx & 127) * 4;
        int lt = tile * TTILE + tr;     // 0..51
        if (lt > T_PER_SPLIT - 1) lt = T_PER_SPLIT - 1;   // clamp (masked -inf)
        int gt = s * T_PER_SPLIT + lt;  // <= 199
        const float* src = (gt < HIST) ? (prevb + (long)gt * 512 + c) : (curb + c);
        cp16(dst + tr * 512 + c, src);
    }
}

__global__ void __launch_bounds__(256) k_attn(
    const float* __restrict__ cur, const float* __restrict__ prev,
    const float* __restrict__ mask, const float* __restrict__ bk)
{
    __shared__ __align__(16) float xb[NBUF][TTILE][DM];      // 40 KB
    __shared__ __align__(16) float s_part[2][8][8][TTILE];   // 2 KB
    __shared__ float mask_s[(NT_SPLIT + 1) * TTILE];         // 56 (padded)
    __shared__ float sb_s[8];

    const int tid = threadIdx.x;
    const int b = blockIdx.x;
    const int s = blockIdx.y;
    const int w = tid >> 5, lane = tid & 31;
    const int h = lane >> 2, g = lane & 3;

    const float* prevb = prev + (long)b * HIST * 512;
    const float* curb  = cur  + (long)b * 512;

    if (tid < (NT_SPLIT + 1) * TTILE)
        mask_s[tid] = (tid < T_PER_SPLIT)
            ? mask[b * TT + s * T_PER_SPLIT + tid] : -CUDART_INF_F;
    {   // sb[h] = q[b,h,:]·bk[h,:]; warp w handles head w
        float q1 = g_q[b * 512 + w * 64 + lane];
        float q2 = g_q[b * 512 + w * 64 + 32 + lane];
        float sv = q1 * bk[w * 64 + lane] + q2 * bk[w * 64 + 32 + lane];
#pragma unroll
        for (int o = 16; o; o >>= 1) sv += __shfl_xor_sync(0xffffffffu, sv, o);
        if (lane == 0) sb_s[w] = sv;
    }

    // r fragment: 4 strided float4 chunks (matches x-access mapping)
    u64 rf[8];
    {
        const float* rp = &g_r[(long)b * 4096 + h * 512 + w * 64 + g * 4];
#pragma unroll
        for (int c = 0; c < 4; c++) {
            ulonglong2 v = *(const ulonglong2*)(rp + 16 * c);
            rf[2 * c + 0] = v.x;
            rf[2 * c + 1] = v.y;
        }
    }
    u64 acc[8];
#pragma unroll
    for (int i = 0; i < 8; i++) acc[i] = 0ull;
    float m = -CUDART_INF_F, l = 0.f;

    // prime 3 tiles (groups 0..2)
#pragma unroll
    for (int i = 0; i < 3; i++) {
        prefetch_tile_s(&xb[i][0][0], prevb, curb, s, i, tid);
        cp_commit();
    }
    __syncthreads();                       // sb_s / mask_s visible
    const float sb = sb_s[h];

    const int joff = w * 64 + g * 4;

    for (int it = 0; it <= NT_SPLIT; it++) {
        if (it < NT_SPLIT) cp_wait2();     // group `it` complete (2 newer pend)
        __syncthreads();                   // the ONLY barrier per iteration

        // keep 3 tiles of lead; target buf (it+3)%5 was last read at iter it-1
        if (it + 3 < NT_SPLIT)
            prefetch_tile_s(&xb[(it + 3) % NBUF][0][0], prevb, curb, s, it + 3, tid);
        if (it < NT_SPLIT) cp_commit();    // uniform group count (may be empty)

        // ---- scores(it) -> s_part[it&1] ----
        if (it < NT_SPLIT) {
            const float* xbase = &xb[it % NBUF][0][joff];
#pragma unroll
            for (int t = 0; t < TTILE; t++) {
                const float* xr = xbase + t * DM;
                ulonglong2 x0 = *(const ulonglong2*)(xr);
                ulonglong2 x1 = *(const ulonglong2*)(xr + 16);
                ulonglong2 x2 = *(const ulonglong2*)(xr + 32);
                ulonglong2 x3 = *(const ulonglong2*)(xr + 48);
                u64 sa = 0ull, sc = 0ull;
                ffma2(sa, rf[0], x0.x); ffma2(sc, rf[1], x0.y);
                ffma2(sa, rf[2], x1.x); ffma2(sc, rf[3], x1.y);
                ffma2(sa, rf[4], x2.x); ffma2(sc, rf[5], x2.y);
                ffma2(sa, rf[6], x3.x); ffma2(sc, rf[7], x3.y);
                float2 fa = unpack2(sa), fc = unpack2(sc);
                float sv = (fa.x + fa.y) + (fc.x + fc.y);
                sv += __shfl_xor_sync(0xffffffffu, sv, 1);
                sv += __shfl_xor_sync(0xffffffffu, sv, 2);
                if (g == 0) s_part[it & 1][w][h][t] = sv;
            }
        }

        // ---- softmax + accumulate for tile it-1 (overlaps scores(it)) ----
        if (it > 0) {
            const int pt = it - 1;
            const float* xbase = &xb[pt % NBUF][0][joff];

            float4 a0 = make_float4(0.f, 0.f, 0.f, 0.f);
#pragma unroll
            for (int w2 = 0; w2 < 8; w2++) {
                float4 v = *(const float4*)&s_part[pt & 1][w2][h][0];
                a0.x += v.x; a0.y += v.y; a0.z += v.z; a0.w += v.w;
            }
            const float* mk = &mask_s[pt * TTILE];
            float lg0 = (a0.x + sb) * 0.125f + mk[0];
            float lg1 = (a0.y + sb) * 0.125f + mk[1];
            float lg2 = (a0.z + sb) * 0.125f + mk[2];
            float lg3 = (a0.w + sb) * 0.125f + mk[3];
            float mx = fmaxf(fmaxf(lg0, lg1), fmaxf(lg2, lg3));
            float m_new = fmaxf(m, mx);
            float p[TTILE];
            p[0] = __expf(lg0 - m_new); p[1] = __expf(lg1 - m_new);
            p[2] = __expf(lg2 - m_new); p[3] = __expf(lg3 - m_new);
            float ps = (p[0] + p[1]) + (p[2] + p[3]);
            float scl = __expf(m - m_new);
            l = l * scl + ps;
            m = m_new;

            u64 sclp = pack2(scl, scl);
#pragma unroll
            for (int i = 0; i < 8; i++) fmul2(acc[i], sclp);
#pragma unroll
            for (int t = 0; t < TTILE; t++) {
                const float* xr = xbase + t * DM;
                ulonglong2 x0 = *(const ulonglong2*)(xr);
                ulonglong2 x1 = *(const ulonglong2*)(xr + 16);
                ulonglong2 x2 = *(const ulonglong2*)(xr + 32);
                ulonglong2 x3 = *(const ulonglong2*)(xr + 48);
                u64 pv = pack2(p[t], p[t]);
                ffma2(acc[0], pv, x0.x); ffma2(acc[1], pv, x0.y);
                ffma2(acc[2], pv, x1.x); ffma2(acc[3], pv, x1.y);
                ffma2(acc[4], pv, x2.x); ffma2(acc[5], pv, x2.y);
                ffma2(acc[6], pv, x3.x); ffma2(acc[7], pv, x3.y);
            }
        }
    }

    // ---- write UNNORMALIZED partial + (m, l) ----
    float* cpo = &g_pc[((long)(b * TSPLIT + s) * 8 + h) * 512 + joff];
#pragma unroll
    for (int c = 0; c < 4; c++) {
        float2 v0 = unpack2(acc[2 * c + 0]);
        float2 v1 = unpack2(acc[2 * c + 1]);
        float4 o = make_float4(v0.x, v0.y, v1.x, v1.y);
        *(float4*)(cpo + 16 * c) = o;
    }
    if (w == 0 && g == 0) {                 // lanes h=0..7, one per head
        g_pml[(b * TSPLIT + s) * 16 + h]     = m;
        g_pml[(b * TSPLIT + s) * 16 + 8 + h] = l;
    }
}

// ============================================================================
// Kernel M: merge 4 split partials -> g_c.  grid 1024, block 256.
// ============================================================================
__global__ void __launch_bounds__(256) k_merge()
{
    __shared__ float wol[TSPLIT][8];
    const int tid = threadIdx.x;
    const int b = blockIdx.x;

    if (tid < 32) {
        int s = tid >> 3, h = tid & 7;
        float m = g_pml[(b * TSPLIT + s) * 16 + h];
        float l = g_pml[(b * TSPLIT + s) * 16 + 8 + h];
        float M = m;
        M = fmaxf(M, __shfl_xor_sync(0xffffffffu, M, 8));
        M = fmaxf(M, __shfl_xor_sync(0xffffffffu, M, 16));
        float wgt = __expf(m - M);
        float wl = wgt * l;
        wl += __shfl_xor_sync(0xffffffffu, wl, 8);
        wl += __shfl_xor_sync(0xffffffffu, wl, 16);
        wol[s][h] = wgt / wl;
    }
    __syncthreads();

#pragma unroll
    for (int c = 0; c < 4; c++) {
        int j = c * 1024 + tid * 4;
        int h = j >> 9;
        float4 a = make_float4(0.f, 0.f, 0.f, 0.f);
#pragma unroll
        for (int s = 0; s < TSPLIT; s++) {
            float4 v = *(const float4*)&g_pc[((long)(b * TSPLIT + s)) * 4096 + j];
            float wv = wol[s][h];
            a.x += wv * v.x; a.y += wv * v.y;
            a.z += wv * v.z; a.w += wv * v.w;
        }
        *(float4*)&g_c[(long)b * 4096 + j] = a;
    }
}

// ============================================================================
extern "C" void kernel_launch(void* const* d_in, const int* in_sizes, int n_in,
                              void* d_out, int out_size)
{
    const float* cur  = (const float*)d_in[0];   // [1024, 512]
    const float* prev = (const float*)d_in[1];   // [1024, 199, 512]
    const float* mask = (const float*)d_in[2];   // [1024, 200]
    const float* Wq   = (const float*)d_in[3];   // [512, 512]
    const float* bq   = (const float*)d_in[4];   // [512]
    const float* Wk   = (const float*)d_in[5];   // [512, 512]
    const float* bk   = (const float*)d_in[6];   // [512]
    const float* Wv   = (const float*)d_in[7];   // [512, 512]
    const float* bv   = (const float*)d_in[8];   // [512]
    float* out = (float*)d_out;                  // [1024, 512]

    // q = cur @ Wq^T + bq          (writes g_q internally)
    k_gemm64<true ><<<dim3(32, 8), 256>>>(cur, Wq, bq, nullptr);
    // r[b,h,:] = Wk_h^T q_h        (g_q -> g_r)
    k_rproj<<<dim3(4, 32, 8), 256>>>(Wk);
    // split-T pipelined attention  (-> g_pc, g_pml)
    k_attn <<<dim3(1024, TSPLIT), 256>>>(cur, prev, mask, bk);
    // merge partials               (-> g_c)
    k_merge<<<1024, 256>>>();
    // out = c @ Wv_h^T + bv        (reads g_c internally)
    k_gemm64<false><<<dim3(32, 8), 256>>>(nullptr, Wv, bv, out);
}

// round 14
// speedup vs baseline: 2.3255x; 1.4253x over previous
#include <cuda_runtime.h>
#include <math_constants.h>

#define BS   1024
#define DM   512
#define NH   8
#define DK   64
#define HIST 199
#define TT   200
#define TTILE 4
#define NBUF 5
#define NTILES 50
#define PSPLIT 2

// Scratch — referenced ONLY inside device code (host-side use passes the host
// shadow address; ATS makes it silently dereferenceable -> garbage).
__device__ float g_q[BS * DM];                     // 2 MB
__device__ float g_r[BS * NH * DM];                // 16 MB
__device__ float g_c[BS * NH * DM];                // 16 MB
__device__ float g_pc[BS * PSPLIT * NH * DM];      // 32 MB  unnormalized partial c
__device__ float g_pml[BS * PSPLIT * 16];          // 128 KB m[8], l[8] per (b,s)

typedef unsigned long long u64;

// ---- packed f32x2 helpers --------------------------------------------------
__device__ __forceinline__ u64 pack2(float x, float y) {
    u64 r; asm("mov.b64 %0, {%1, %2};" : "=l"(r) : "f"(x), "f"(y)); return r;
}
__device__ __forceinline__ float2 unpack2(u64 v) {
    float2 d; asm("mov.b64 {%0, %1}, %2;" : "=f"(d.x), "=f"(d.y) : "l"(v)); return d;
}
__device__ __forceinline__ void ffma2(u64& acc, u64 a, u64 b) {
    asm("fma.rn.f32x2 %0, %1, %2, %0;" : "+l"(acc) : "l"(a), "l"(b));
}
__device__ __forceinline__ void fmul2(u64& a, u64 b) {
    asm("mul.rn.f32x2 %0, %0, %1;" : "+l"(a) : "l"(b));
}
__device__ __forceinline__ void ldg16(const float* p, u64& a, u64& b) {
    asm volatile("ld.global.nc.v2.b64 {%0, %1}, [%2];" : "=l"(a), "=l"(b) : "l"(p));
}
__device__ __forceinline__ void cp16(void* smem_dst, const void* gsrc) {
    unsigned s = (unsigned)__cvta_generic_to_shared(smem_dst);
    asm volatile("cp.async.cg.shared.global [%0], [%1], 16;" :: "r"(s), "l"(gsrc));
}
__device__ __forceinline__ void cp_commit() { asm volatile("cp.async.commit_group;" ::: "memory"); }
__device__ __forceinline__ void cp_wait2()  { asm volatile("cp.async.wait_group 2;" ::: "memory"); }
__device__ __forceinline__ void cp_wait1()  { asm volatile("cp.async.wait_group 1;" ::: "memory"); }

// ============================================================================
// Kernel G (measured 24us): 32b x 64d NT GEMM, K=512, grid (32,8).
// ============================================================================
__device__ __forceinline__ int swz(int cj, int row) { return 4 * (cj ^ ((row >> 1) & 7)); }

template<bool QPROJ>
__global__ void __launch_bounds__(256) k_gemm64(
    const float* __restrict__ Aext, const float* __restrict__ B,
    const float* __restrict__ bias, float* __restrict__ outext)
{
    __shared__ __align__(16) float Cs[2][32][32];
    __shared__ __align__(16) float Ws[2][64][32];
    const int tid = threadIdx.x;
    const int bB = blockIdx.x * 32;
    const int y  = blockIdx.y;
    const float* Bb = B + (long)y * 64 * 512;
    const int d0 = (tid >> 4) * 4;
    const int b0 = (tid & 15) * 2;

    const float* Abase = QPROJ ? Aext : (const float*)g_c;
    const long a_rstride = QPROJ ? 512 : 4096;
    const long a_yoff    = QPROJ ? 0   : (long)y * 512;

    u64 acc[2][4];
#pragma unroll
    for (int cb = 0; cb < 2; cb++)
#pragma unroll
        for (int dd = 0; dd < 4; dd++) acc[cb][dd] = 0ull;

    {
        int row = tid >> 3, cj = tid & 7;
        cp16(&Cs[0][row][swz(cj, row)],
             Abase + (long)(bB + row) * a_rstride + a_yoff + cj * 4);
    }
#pragma unroll
    for (int i = 0; i < 2; i++) {
        int idx = tid + 256 * i;
        int d = idx >> 3, cj = idx & 7;
        cp16(&Ws[0][d][swz(cj, d)], Bb + (long)d * 512 + cj * 4);
    }
    cp_commit();

    for (int kc = 0; kc < 16; kc++) {
        const int buf = kc & 1;
        if (kc + 1 < 16) {
            {
                int row = tid >> 3, cj = tid & 7;
                cp16(&Cs[buf ^ 1][row][swz(cj, row)],
                     Abase + (long)(bB + row) * a_rstride + a_yoff + (kc + 1) * 32 + cj * 4);
            }
#pragma unroll
            for (int i = 0; i < 2; i++) {
                int idx = tid + 256 * i;
                int d = idx >> 3, cj = idx & 7;
                cp16(&Ws[buf ^ 1][d][swz(cj, d)],
                     Bb + (long)d * 512 + (kc + 1) * 32 + cj * 4);
            }
        }
        cp_commit();
        cp_wait1();
        __syncthreads();

#pragma unroll
        for (int jg = 0; jg < 8; jg++) {
            ulonglong2 wv[4], cv[2];
#pragma unroll
            for (int dd = 0; dd < 4; dd++)
                wv[dd] = *(const ulonglong2*)&Ws[buf][d0 + dd][swz(jg, d0 + dd)];
#pragma unroll
            for (int cb = 0; cb < 2; cb++)
                cv[cb] = *(const ulonglong2*)&Cs[buf][b0 + cb][swz(jg, b0 + cb)];
#pragma unroll
            for (int cb = 0; cb < 2; cb++)
#pragma unroll
                for (int dd = 0; dd < 4; dd++) {
                    ffma2(acc[cb][dd], cv[cb].x, wv[dd].x);
                    ffma2(acc[cb][dd], cv[cb].y, wv[dd].y);
                }
        }
        __syncthreads();
    }

    float* Out = QPROJ ? (float*)g_q : outext;
    float4 bb = *(const float4*)&bias[y * 64 + d0];
#pragma unroll
    for (int cb = 0; cb < 2; cb++) {
        float v[4];
#pragma unroll
        for (int dd = 0; dd < 4; dd++) {
            float2 u = unpack2(acc[cb][dd]);
            v[dd] = u.x + u.y;
        }
        float4 o = make_float4(v[0] + bb.x, v[1] + bb.y, v[2] + bb.z, v[3] + bb.w);
        *(float4*)&Out[(long)(bB + b0 + cb) * 512 + y * 64 + d0] = o;
    }
}

// ============================================================================
// Kernel B: r[b,h,n] = sum_k q[b, h*64+k] * Wk[h*64+k, n]   (NN, K=64)
// ============================================================================
__global__ void __launch_bounds__(256) k_rproj(const float* __restrict__ Wk)
{
    __shared__ __align__(16) float Wks[64][128];
    __shared__ __align__(16) float qs[32][64];
    const int tid = threadIdx.x;
    const int nc = blockIdx.x;
    const int bB = blockIdx.y * 32;
    const int h  = blockIdx.z;

#pragma unroll
    for (int it = 0; it < 8; it++) {
        int idx = tid + 256 * it;
        int k = idx >> 5, n4 = (idx & 31) * 4;
        *(float4*)&Wks[k][n4] = *(const float4*)&Wk[(h * 64 + k) * 512 + nc * 128 + n4];
    }
#pragma unroll
    for (int it = 0; it < 2; it++) {
        int idx = tid + 256 * it;
        int bb = idx >> 4, k4 = (idx & 15) * 4;
        *(float4*)&qs[bb][k4] = *(const float4*)&g_q[(bB + bb) * 512 + h * 64 + k4];
    }
    __syncthreads();

    const int n0 = (tid & 31) * 4;
    const int b0 = (tid >> 5) * 4;
    u64 acc[4][2];
#pragma unroll
    for (int a = 0; a < 4; a++) { acc[a][0] = 0ull; acc[a][1] = 0ull; }

#pragma unroll
    for (int k = 0; k < 64; k++) {
        ulonglong2 w2 = *(const ulonglong2*)&Wks[k][n0];
#pragma unroll
        for (int cb = 0; cb < 4; cb++) {
            float x = qs[b0 + cb][k];
            u64 xx = pack2(x, x);
            ffma2(acc[cb][0], xx, w2.x);
            ffma2(acc[cb][1], xx, w2.y);
        }
    }
#pragma unroll
    for (int cb = 0; cb < 4; cb++) {
        float2 p0 = unpack2(acc[cb][0]), p1 = unpack2(acc[cb][1]);
        float4 o = make_float4(p0.x, p0.y, p1.x, p1.y);
        *(float4*)&g_r[((bB + b0 + cb) * 8 + h) * 512 + nc * 128 + n0] = o;
    }
}

// ============================================================================
// Kernel C: LANE-DISTINCT attention. 1 CTA / batch row, 8 warps.
// Warp w: head-pair hp = w&3 (heads 2hp, 2hp+1), t-parity par = w>>2.
// Lane owns j in {4*lane + 128*c, c=0..3} (16 distinct floats). Every LDS.128
// is 512B contiguous conflict-free; x delivered ONCE per warp per timestep
// and kept in registers through scores -> softmax -> accumulate.
// Per tile (4 t): warp processes t = tile*4 + par, tile*4 + par + 2.
// (m, l, acc) are parity-local; k_merge combines the 2 parity partials.
// One __syncthreads per tile; warp-butterfly score reduction (no s_part).
// ============================================================================
__device__ __forceinline__ void prefetch_tile(
    float* dst, const float* __restrict__ prevb, const float* __restrict__ curb,
    int tile, int tid)
{
#pragma unroll
    for (int i = 0; i < 2; i++) {
        int idx = tid + 256 * i;        // 512 float4 = 4 rows x 512 floats
        int tr = idx >> 7;
        int c = (idx & 127) * 4;
        int gt = tile * TTILE + tr;     // <= 199 (50*4 = 200 exact)
        const float* src = (gt < HIST) ? (prevb + (long)gt * 512 + c) : (curb + c);
        cp16(dst + tr * 512 + c, src);
    }
}

__device__ __forceinline__ float bfly_sum(float s) {
#pragma unroll
    for (int o = 16; o; o >>= 1) s += __shfl_xor_sync(0xffffffffu, s, o);
    return s;
}

__global__ void __launch_bounds__(256, 2) k_attn(
    const float* __restrict__ cur, const float* __restrict__ prev,
    const float* __restrict__ mask, const float* __restrict__ bk)
{
    __shared__ __align__(16) float xb[NBUF][TTILE][DM];   // 40 KB
    __shared__ float mask_s[TT];
    __shared__ float sb_s[8];

    const int tid = threadIdx.x;
    const int b = blockIdx.x;
    const int w = tid >> 5, lane = tid & 31;
    const int hp = w & 3, par = w >> 2;
    const int h0 = 2 * hp, h1 = 2 * hp + 1;

    const float* prevb = prev + (long)b * HIST * 512;
    const float* curb  = cur  + (long)b * 512;

    if (tid < TT) mask_s[tid] = mask[b * TT + tid];
    {   // sb[h] = q[b,h,:]·bk[h,:]; warp w computes head w
        float q1 = g_q[b * 512 + w * 64 + lane];
        float q2 = g_q[b * 512 + w * 64 + 32 + lane];
        float sv = q1 * bk[w * 64 + lane] + q2 * bk[w * 64 + 32 + lane];
        sv = bfly_sum(sv);
        if (lane == 0) sb_s[w] = sv;
    }

    // rf: r[b, h, 4*lane + 128*c] for both heads (16 distinct floats each)
    u64 rf0[8], rf1[8];
    {
        const float* rp0 = &g_r[((long)b * 8 + h0) * 512 + 4 * lane];
        const float* rp1 = &g_r[((long)b * 8 + h1) * 512 + 4 * lane];
#pragma unroll
        for (int c = 0; c < 4; c++) {
            ldg16(rp0 + 128 * c, rf0[2 * c], rf0[2 * c + 1]);
            ldg16(rp1 + 128 * c, rf1[2 * c], rf1[2 * c + 1]);
        }
    }
    u64 acc0[8], acc1[8];
#pragma unroll
    for (int i = 0; i < 8; i++) { acc0[i] = 0ull; acc1[i] = 0ull; }
    float m0 = -CUDART_INF_F, l0 = 0.f;
    float m1 = -CUDART_INF_F, l1 = 0.f;

    // prime 3 tiles
#pragma unroll
    for (int i = 0; i < 3; i++) {
        prefetch_tile(&xb[i][0][0], prevb, curb, i, tid);
        cp_commit();
    }
    __syncthreads();                       // sb_s / mask_s visible
    const float sb0 = sb_s[h0];
    const float sb1 = sb_s[h1];

    for (int tile = 0; tile < NTILES; tile++) {
        const int buf = tile % NBUF;
        cp_wait2();                        // tile's group complete (2 newer pend)
        __syncthreads();                   // the ONLY barrier per tile

        // keep 3 tiles of lead; target buf was last read at tile-2
        if (tile + 3 < NTILES)
            prefetch_tile(&xb[(tile + 3) % NBUF][0][0], prevb, curb, tile + 3, tid);
        cp_commit();                       // uniform group count

        // ---- load x for own 2 timesteps into registers (512B/LDS, 1x) ----
        const float* rA = &xb[buf][par][4 * lane];          // t = tile*4+par
        const float* rB = &xb[buf][par + 2][4 * lane];      // t = tile*4+par+2
        u64 xA[8], xB[8];
#pragma unroll
        for (int c = 0; c < 4; c++) {
            ulonglong2 vA = *(const ulonglong2*)(rA + 128 * c);
            ulonglong2 vB = *(const ulonglong2*)(rB + 128 * c);
            xA[2 * c] = vA.x; xA[2 * c + 1] = vA.y;
            xB[2 * c] = vB.x; xB[2 * c + 1] = vB.y;
        }

        // ---- scores: 4 dot-partials (2 heads x 2 t), butterfly reduce ----
        u64 a00 = 0ull, a01 = 0ull, a10 = 0ull, a11 = 0ull;
        u64 b00 = 0ull, b01 = 0ull, b10 = 0ull, b11 = 0ull;
#pragma unroll
        for (int i = 0; i < 8; i += 2) {
            ffma2(a00, rf0[i], xA[i]);   ffma2(a01, rf0[i + 1], xA[i + 1]);
            ffma2(a10, rf1[i], xA[i]);   ffma2(a11, rf1[i + 1], xA[i + 1]);
            ffma2(b00, rf0[i], xB[i]);   ffma2(b01, rf0[i + 1], xB[i + 1]);
            ffma2(b10, rf1[i], xB[i]);   ffma2(b11, rf1[i + 1], xB[i + 1]);
        }
        float2 u;
        u = unpack2(a00); float sA0 = u.x + u.y; u = unpack2(a01); sA0 += u.x + u.y;
        u = unpack2(a10); float sA1 = u.x + u.y; u = unpack2(a11); sA1 += u.x + u.y;
        u = unpack2(b00); float sB0 = u.x + u.y; u = unpack2(b01); sB0 += u.x + u.y;
        u = unpack2(b10); float sB1 = u.x + u.y; u = unpack2(b11); sB1 += u.x + u.y;
        sA0 = bfly_sum(sA0); sA1 = bfly_sum(sA1);
        sB0 = bfly_sum(sB0); sB1 = bfly_sum(sB1);

        // ---- warp-local online softmax (parity-local m, l) ----
        const int gtA = tile * TTILE + par;
        const int gtB = gtA + 2;
        float lgA0 = (sA0 + sb0) * 0.125f + mask_s[gtA];
        float lgB0 = (sB0 + sb0) * 0.125f + mask_s[gtB];
        float lgA1 = (sA1 + sb1) * 0.125f + mask_s[gtA];
        float lgB1 = (sB1 + sb1) * 0.125f + mask_s[gtB];

        float mx0 = fmaxf(lgA0, lgB0);
        if (mx0 > m0) {
            float scl = __expf(m0 - mx0);  // first tile: exp(-inf) = 0
            u64 sclp = pack2(scl, scl);
#pragma unroll
            for (int i = 0; i < 8; i++) fmul2(acc0[i], sclp);
            l0 *= scl; m0 = mx0;
        }
        float pA0 = __expf(lgA0 - m0), pB0 = __expf(lgB0 - m0);
        l0 += pA0 + pB0;

        float mx1 = fmaxf(lgA1, lgB1);
        if (mx1 > m1) {
            float scl = __expf(m1 - mx1);
            u64 sclp = pack2(scl, scl);
#pragma unroll
            for (int i = 0; i < 8; i++) fmul2(acc1[i], sclp);
            l1 *= scl; m1 = mx1;
        }
        float pA1 = __expf(lgA1 - m1), pB1 = __expf(lgB1 - m1);
        l1 += pA1 + pB1;

        // ---- accumulate from registers (no second smem pass) ----
        u64 pvA0 = pack2(pA0, pA0), pvB0 = pack2(pB0, pB0);
        u64 pvA1 = pack2(pA1, pA1), pvB1 = pack2(pB1, pB1);
#pragma unroll
        for (int i = 0; i < 8; i++) {
            ffma2(acc0[i], pvA0, xA[i]);
            ffma2(acc1[i], pvA1, xA[i]);
            ffma2(acc0[i], pvB0, xB[i]);
            ffma2(acc1[i], pvB1, xB[i]);
        }
    }

    // ---- write UNNORMALIZED parity partials + (m, l) ----
    {
        float* p0 = &g_pc[(((long)b * PSPLIT + par) * 8 + h0) * 512 + 4 * lane];
        float* p1 = &g_pc[(((long)b * PSPLIT + par) * 8 + h1) * 512 + 4 * lane];
#pragma unroll
        for (int c = 0; c < 4; c++) {
            float2 v0 = unpack2(acc0[2 * c]), v1 = unpack2(acc0[2 * c + 1]);
            *(float4*)(p0 + 128 * c) = make_float4(v0.x, v0.y, v1.x, v1.y);
            float2 w0 = unpack2(acc1[2 * c]), w1 = unpack2(acc1[2 * c + 1]);
            *(float4*)(p1 + 128 * c) = make_float4(w0.x, w0.y, w1.x, w1.y);
        }
    }
    if (lane == 0) {
        long base = ((long)b * PSPLIT + par) * 16;
        g_pml[base + h0]     = m0;
        g_pml[base + 8 + h0] = l0;
        g_pml[base + h1]     = m1;
        g_pml[base + 8 + h1] = l1;
    }
}

// ============================================================================
// Kernel M: merge 2 parity partials -> g_c.  grid 1024, block 256.
// ============================================================================
__global__ void __launch_bounds__(256) k_merge()
{
    __shared__ float wol[PSPLIT][8];
    const int tid = threadIdx.x;
    const int b = blockIdx.x;

    if (tid < 32) {
        int s = (tid >> 3) & 1, h = tid & 7;   // lanes 16-31 duplicate 0-15
        float m = g_pml[((long)b * PSPLIT + s) * 16 + h];
        float l = g_pml[((long)b * PSPLIT + s) * 16 + 8 + h];
        float M = fmaxf(m, __shfl_xor_sync(0xffffffffu, m, 8));
        float wgt = __expf(m - M);
        float wl = wgt * l;
        wl += __shfl_xor_sync(0xffffffffu, wl, 8);
        if (tid < 16) wol[s][h] = wgt / wl;
    }
    __syncthreads();

#pragma unroll
    for (int c = 0; c < 4; c++) {
        int j = c * 1024 + tid * 4;
        int h = j >> 9;
        float4 a = make_float4(0.f, 0.f, 0.f, 0.f);
#pragma unroll
        for (int s = 0; s < PSPLIT; s++) {
            float4 v = *(const float4*)&g_pc[((long)b * PSPLIT + s) * 4096 + j];
            float wv = wol[s][h];
            a.x += wv * v.x; a.y += wv * v.y;
            a.z += wv * v.z; a.w += wv * v.w;
        }
        *(float4*)&g_c[(long)b * 4096 + j] = a;
    }
}

// ============================================================================
extern "C" void kernel_launch(void* const* d_in, const int* in_sizes, int n_in,
                              void* d_out, int out_size)
{
    const float* cur  = (const float*)d_in[0];   // [1024, 512]
    const float* prev = (const float*)d_in[1];   // [1024, 199, 512]
    const float* mask = (const float*)d_in[2];   // [1024, 200]
    const float* Wq   = (const float*)d_in[3];   // [512, 512]
    const float* bq   = (const float*)d_in[4];   // [512]
    const float* Wk   = (const float*)d_in[5];   // [512, 512]
    const float* bk   = (const float*)d_in[6];   // [512]
    const float* Wv   = (const float*)d_in[7];   // [512, 512]
    const float* bv   = (const float*)d_in[8];   // [512]
    float* out = (float*)d_out;                  // [1024, 512]

    // q = cur @ Wq^T + bq          (writes g_q internally)
    k_gemm64<true ><<<dim3(32, 8), 256>>>(cur, Wq, bq, nullptr);
    // r[b,h,:] = Wk_h^T q_h        (g_q -> g_r)
    k_rproj<<<dim3(4, 32, 8), 256>>>(Wk);
    // lane-distinct attention      (-> g_pc, g_pml)
    k_attn <<<dim3(1024), 256>>>(cur, prev, mask, bk);
    // merge parity partials        (-> g_c)
    k_merge<<<1024, 256>>>();
    // out = c @ Wv_h^T + bv        (reads g_c internally)
    k_gemm64<false><<<dim3(32, 8), 256>>>(nullptr, Wv, bv, out);
}

// round 15
// speedup vs baseline: 2.4580x; 1.0570x over previous
#include <cuda_runtime.h>
#include <math_constants.h>

#define BS   1024
#define DM   512
#define NH   8
#define DK   64
#define HIST 199
#define TT   200
#define TTILE 8
#define NBUF 3
#define NTILES 25
#define PSPLIT 2

// Scratch — referenced ONLY inside device code (host-side use passes the host
// shadow address; ATS makes it silently dereferenceable -> garbage).
__device__ float g_q[BS * DM];                     // 2 MB
__device__ float g_r[BS * NH * DM];                // 16 MB
__device__ float g_pc[BS * PSPLIT * NH * DM];      // 32 MB  unnormalized partial c
__device__ float g_pml[BS * PSPLIT * 16];          // 128 KB m[8], l[8] per (b,s)

typedef unsigned long long u64;

// ---- packed f32x2 helpers --------------------------------------------------
__device__ __forceinline__ u64 pack2(float x, float y) {
    u64 r; asm("mov.b64 %0, {%1, %2};" : "=l"(r) : "f"(x), "f"(y)); return r;
}
__device__ __forceinline__ float2 unpack2(u64 v) {
    float2 d; asm("mov.b64 {%0, %1}, %2;" : "=f"(d.x), "=f"(d.y) : "l"(v)); return d;
}
__device__ __forceinline__ void ffma2(u64& acc, u64 a, u64 b) {
    asm("fma.rn.f32x2 %0, %1, %2, %0;" : "+l"(acc) : "l"(a), "l"(b));
}
__device__ __forceinline__ void fmul2(u64& a, u64 b) {
    asm("mul.rn.f32x2 %0, %0, %1;" : "+l"(a) : "l"(b));
}
__device__ __forceinline__ void ldg16(const float* p, u64& a, u64& b) {
    asm volatile("ld.global.nc.v2.b64 {%0, %1}, [%2];" : "=l"(a), "=l"(b) : "l"(p));
}
__device__ __forceinline__ void cp16(void* smem_dst, const void* gsrc) {
    unsigned s = (unsigned)__cvta_generic_to_shared(smem_dst);
    asm volatile("cp.async.cg.shared.global [%0], [%1], 16;" :: "r"(s), "l"(gsrc));
}
__device__ __forceinline__ void cp_commit() { asm volatile("cp.async.commit_group;" ::: "memory"); }
__device__ __forceinline__ void cp_wait1()  { asm volatile("cp.async.wait_group 1;" ::: "memory"); }

__device__ __forceinline__ int swz(int cj, int row) { return 4 * (cj ^ ((row >> 1) & 7)); }

// ============================================================================
// Kernel A: qproj GEMM (measured ~10us): 32b x 64d NT, K=512, grid (32,8).
// g_q[b, y*64+d] = sum_k cur[b,k] * Wq[(y*64+d)*512+k] + bq
// ============================================================================
__global__ void __launch_bounds__(256) k_qproj(
    const float* __restrict__ A, const float* __restrict__ B,
    const float* __restrict__ bias)
{
    __shared__ __align__(16) float Cs[2][32][32];
    __shared__ __align__(16) float Ws[2][64][32];
    const int tid = threadIdx.x;
    const int bB = blockIdx.x * 32;
    const int y  = blockIdx.y;
    const float* Bb = B + (long)y * 64 * 512;
    const int d0 = (tid >> 4) * 4;
    const int b0 = (tid & 15) * 2;

    u64 acc[2][4];
#pragma unroll
    for (int cb = 0; cb < 2; cb++)
#pragma unroll
        for (int dd = 0; dd < 4; dd++) acc[cb][dd] = 0ull;

    {
        int row = tid >> 3, cj = tid & 7;
        cp16(&Cs[0][row][swz(cj, row)], A + (long)(bB + row) * 512 + cj * 4);
    }
#pragma unroll
    for (int i = 0; i < 2; i++) {
        int idx = tid + 256 * i;
        int d = idx >> 3, cj = idx & 7;
        cp16(&Ws[0][d][swz(cj, d)], Bb + (long)d * 512 + cj * 4);
    }
    cp_commit();

    for (int kc = 0; kc < 16; kc++) {
        const int buf = kc & 1;
        if (kc + 1 < 16) {
            {
                int row = tid >> 3, cj = tid & 7;
                cp16(&Cs[buf ^ 1][row][swz(cj, row)],
                     A + (long)(bB + row) * 512 + (kc + 1) * 32 + cj * 4);
            }
#pragma unroll
            for (int i = 0; i < 2; i++) {
                int idx = tid + 256 * i;
                int d = idx >> 3, cj = idx & 7;
                cp16(&Ws[buf ^ 1][d][swz(cj, d)],
                     Bb + (long)d * 512 + (kc + 1) * 32 + cj * 4);
            }
        }
        cp_commit();
        cp_wait1();
        __syncthreads();

#pragma unroll
        for (int jg = 0; jg < 8; jg++) {
            ulonglong2 wv[4], cv[2];
#pragma unroll
            for (int dd = 0; dd < 4; dd++)
                wv[dd] = *(const ulonglong2*)&Ws[buf][d0 + dd][swz(jg, d0 + dd)];
#pragma unroll
            for (int cb = 0; cb < 2; cb++)
                cv[cb] = *(const ulonglong2*)&Cs[buf][b0 + cb][swz(jg, b0 + cb)];
#pragma unroll
            for (int cb = 0; cb < 2; cb++)
#pragma unroll
                for (int dd = 0; dd < 4; dd++) {
                    ffma2(acc[cb][dd], cv[cb].x, wv[dd].x);
                    ffma2(acc[cb][dd], cv[cb].y, wv[dd].y);
                }
        }
        __syncthreads();
    }

    float4 bb = *(const float4*)&bias[y * 64 + d0];
#pragma unroll
    for (int cb = 0; cb < 2; cb++) {
        float v[4];
#pragma unroll
        for (int dd = 0; dd < 4; dd++) {
            float2 u = unpack2(acc[cb][dd]);
            v[dd] = u.x + u.y;
        }
        float4 o = make_float4(v[0] + bb.x, v[1] + bb.y, v[2] + bb.z, v[3] + bb.w);
        *(float4*)&g_q[(long)(bB + b0 + cb) * 512 + y * 64 + d0] = o;
    }
}

// ============================================================================
// Kernel B: r[b,h,n] = sum_k q[b, h*64+k] * Wk[h*64+k, n]   (NN, K=64)
// ============================================================================
__global__ void __launch_bounds__(256) k_rproj(const float* __restrict__ Wk)
{
    __shared__ __align__(16) float Wks[64][128];
    __shared__ __align__(16) float qs[32][64];
    const int tid = threadIdx.x;
    const int nc = blockIdx.x;
    const int bB = blockIdx.y * 32;
    const int h  = blockIdx.z;

#pragma unroll
    for (int it = 0; it < 8; it++) {
        int idx = tid + 256 * it;
        int k = idx >> 5, n4 = (idx & 31) * 4;
        *(float4*)&Wks[k][n4] = *(const float4*)&Wk[(h * 64 + k) * 512 + nc * 128 + n4];
    }
#pragma unroll
    for (int it = 0; it < 2; it++) {
        int idx = tid + 256 * it;
        int bb = idx >> 4, k4 = (idx & 15) * 4;
        *(float4*)&qs[bb][k4] = *(const float4*)&g_q[(bB + bb) * 512 + h * 64 + k4];
    }
    __syncthreads();

    const int n0 = (tid & 31) * 4;
    const int b0 = (tid >> 5) * 4;
    u64 acc[4][2];
#pragma unroll
    for (int a = 0; a < 4; a++) { acc[a][0] = 0ull; acc[a][1] = 0ull; }

#pragma unroll
    for (int k = 0; k < 64; k++) {
        ulonglong2 w2 = *(const ulonglong2*)&Wks[k][n0];
#pragma unroll
        for (int cb = 0; cb < 4; cb++) {
            float x = qs[b0 + cb][k];
            u64 xx = pack2(x, x);
            ffma2(acc[cb][0], xx, w2.x);
            ffma2(acc[cb][1], xx, w2.y);
        }
    }
#pragma unroll
    for (int cb = 0; cb < 4; cb++) {
        float2 p0 = unpack2(acc[cb][0]), p1 = unpack2(acc[cb][1]);
        float4 o = make_float4(p0.x, p0.y, p1.x, p1.y);
        *(float4*)&g_r[((bB + b0 + cb) * 8 + h) * 512 + nc * 128 + n0] = o;
    }
}

// ============================================================================
// Kernel C: LANE-DISTINCT attention, TTILE=8 (2 register subpasses / barrier).
// Warp w: head-pair hp = w&3, t-parity par = w>>2. Lane owns 16 distinct j's
// {4*lane + 128c}. Per tile of 8 t: subpass s handles t = tile*8 + 4s + par,
// +2. One __syncthreads per tile (25 total); x in registers through
// scores -> softmax -> accumulate; parity partials merged in k_oproj_fused.
// ============================================================================
__device__ __forceinline__ void prefetch_tile(
    float* dst, const float* __restrict__ prevb, const float* __restrict__ curb,
    int tile, int tid)
{
#pragma unroll
    for (int i = 0; i < 4; i++) {
        int idx = tid + 256 * i;        // 1024 float4 = 8 rows x 512 floats
        int tr = idx >> 7;
        int c = (idx & 127) * 4;
        int gt = tile * TTILE + tr;     // <= 199 (25*8 = 200 exact)
        const float* src = (gt < HIST) ? (prevb + (long)gt * 512 + c) : (curb + c);
        cp16(dst + tr * 512 + c, src);
    }
}

__device__ __forceinline__ float bfly_sum(float s) {
#pragma unroll
    for (int o = 16; o; o >>= 1) s += __shfl_xor_sync(0xffffffffu, s, o);
    return s;
}

__global__ void __launch_bounds__(256, 2) k_attn(
    const float* __restrict__ cur, const float* __restrict__ prev,
    const float* __restrict__ mask, const float* __restrict__ bk)
{
    __shared__ __align__(16) float xb[NBUF][TTILE][DM];   // 48 KB
    __shared__ float mask_s[TT];
    __shared__ float sb_s[8];

    const int tid = threadIdx.x;
    const int b = blockIdx.x;
    const int w = tid >> 5, lane = tid & 31;
    const int hp = w & 3, par = w >> 2;
    const int h0 = 2 * hp, h1 = 2 * hp + 1;

    const float* prevb = prev + (long)b * HIST * 512;
    const float* curb  = cur  + (long)b * 512;

    if (tid < TT) mask_s[tid] = mask[b * TT + tid];
    {   // sb[h] = q[b,h,:]·bk[h,:]; warp w computes head w
        float q1 = g_q[b * 512 + w * 64 + lane];
        float q2 = g_q[b * 512 + w * 64 + 32 + lane];
        float sv = q1 * bk[w * 64 + lane] + q2 * bk[w * 64 + 32 + lane];
        sv = bfly_sum(sv);
        if (lane == 0) sb_s[w] = sv;
    }

    // rf: r[b, h, 4*lane + 128*c] for both heads (16 distinct floats each)
    u64 rf0[8], rf1[8];
    {
        const float* rp0 = &g_r[((long)b * 8 + h0) * 512 + 4 * lane];
        const float* rp1 = &g_r[((long)b * 8 + h1) * 512 + 4 * lane];
#pragma unroll
        for (int c = 0; c < 4; c++) {
            ldg16(rp0 + 128 * c, rf0[2 * c], rf0[2 * c + 1]);
            ldg16(rp1 + 128 * c, rf1[2 * c], rf1[2 * c + 1]);
        }
    }
    u64 acc0[8], acc1[8];
#pragma unroll
    for (int i = 0; i < 8; i++) { acc0[i] = 0ull; acc1[i] = 0ull; }
    float m0 = -CUDART_INF_F, l0 = 0.f;
    float m1 = -CUDART_INF_F, l1 = 0.f;

    // prime 2 tiles
#pragma unroll
    for (int i = 0; i < 2; i++) {
        prefetch_tile(&xb[i][0][0], prevb, curb, i, tid);
        cp_commit();
    }
    __syncthreads();                       // sb_s / mask_s visible
    const float sb0 = sb_s[h0];
    const float sb1 = sb_s[h1];

    for (int tile = 0; tile < NTILES; tile++) {
        const int buf = tile % NBUF;
        cp_wait1();                        // tile's group complete (1 newer pend)
        __syncthreads();                   // the ONLY barrier per tile

        // keep 2 tiles of lead; target buf (tile+2)%3 last read at tile-1
        if (tile + 2 < NTILES)
            prefetch_tile(&xb[(tile + 2) % NBUF][0][0], prevb, curb, tile + 2, tid);
        cp_commit();                       // uniform group count

#pragma unroll
        for (int sub = 0; sub < 2; sub++) {
            // ---- load x for own 2 timesteps into registers ----
            const int tA = 4 * sub + par;
            const float* rA = &xb[buf][tA][4 * lane];
            const float* rB = &xb[buf][tA + 2][4 * lane];
            u64 xA[8], xB[8];
#pragma unroll
            for (int c = 0; c < 4; c++) {
                ulonglong2 vA = *(const ulonglong2*)(rA + 128 * c);
                ulonglong2 vB = *(const ulonglong2*)(rB + 128 * c);
                xA[2 * c] = vA.x; xA[2 * c + 1] = vA.y;
                xB[2 * c] = vB.x; xB[2 * c + 1] = vB.y;
            }

            // ---- scores: 4 dot-partials (2 heads x 2 t), butterfly reduce ----
            u64 a00 = 0ull, a01 = 0ull, a10 = 0ull, a11 = 0ull;
            u64 b00 = 0ull, b01 = 0ull, b10 = 0ull, b11 = 0ull;
#pragma unroll
            for (int i = 0; i < 8; i += 2) {
                ffma2(a00, rf0[i], xA[i]);   ffma2(a01, rf0[i + 1], xA[i + 1]);
                ffma2(a10, rf1[i], xA[i]);   ffma2(a11, rf1[i + 1], xA[i + 1]);
                ffma2(b00, rf0[i], xB[i]);   ffma2(b01, rf0[i + 1], xB[i + 1]);
                ffma2(b10, rf1[i], xB[i]);   ffma2(b11, rf1[i + 1], xB[i + 1]);
            }
            float2 u;
            u = unpack2(a00); float sA0 = u.x + u.y; u = unpack2(a01); sA0 += u.x + u.y;
            u = unpack2(a10); float sA1 = u.x + u.y; u = unpack2(a11); sA1 += u.x + u.y;
            u = unpack2(b00); float sB0 = u.x + u.y; u = unpack2(b01); sB0 += u.x + u.y;
            u = unpack2(b10); float sB1 = u.x + u.y; u = unpack2(b11); sB1 += u.x + u.y;
            sA0 = bfly_sum(sA0); sA1 = bfly_sum(sA1);
            sB0 = bfly_sum(sB0); sB1 = bfly_sum(sB1);

            // ---- warp-local online softmax (parity-local m, l) ----
            const int gtA = tile * TTILE + tA;
            const int gtB = gtA + 2;
            float lgA0 = (sA0 + sb0) * 0.125f + mask_s[gtA];
            float lgB0 = (sB0 + sb0) * 0.125f + mask_s[gtB];
            float lgA1 = (sA1 + sb1) * 0.125f + mask_s[gtA];
            float lgB1 = (sB1 + sb1) * 0.125f + mask_s[gtB];

            float mx0 = fmaxf(lgA0, lgB0);
            if (mx0 > m0) {
                float scl = __expf(m0 - mx0);  // first: exp(-inf) = 0
                u64 sclp = pack2(scl, scl);
#pragma unroll
                for (int i = 0; i < 8; i++) fmul2(acc0[i], sclp);
                l0 *= scl; m0 = mx0;
            }
            float pA0 = __expf(lgA0 - m0), pB0 = __expf(lgB0 - m0);
            l0 += pA0 + pB0;

            float mx1 = fmaxf(lgA1, lgB1);
            if (mx1 > m1) {
                float scl = __expf(m1 - mx1);
                u64 sclp = pack2(scl, scl);
#pragma unroll
                for (int i = 0; i < 8; i++) fmul2(acc1[i], sclp);
                l1 *= scl; m1 = mx1;
            }
            float pA1 = __expf(lgA1 - m1), pB1 = __expf(lgB1 - m1);
            l1 += pA1 + pB1;

            // ---- accumulate from registers ----
            u64 pvA0 = pack2(pA0, pA0), pvB0 = pack2(pB0, pB0);
            u64 pvA1 = pack2(pA1, pA1), pvB1 = pack2(pB1, pB1);
#pragma unroll
            for (int i = 0; i < 8; i++) {
                ffma2(acc0[i], pvA0, xA[i]);
                ffma2(acc1[i], pvA1, xA[i]);
                ffma2(acc0[i], pvB0, xB[i]);
                ffma2(acc1[i], pvB1, xB[i]);
            }
        }
    }

    // ---- write UNNORMALIZED parity partials + (m, l) ----
    {
        float* p0 = &g_pc[(((long)b * PSPLIT + par) * 8 + h0) * 512 + 4 * lane];
        float* p1 = &g_pc[(((long)b * PSPLIT + par) * 8 + h1) * 512 + 4 * lane];
#pragma unroll
        for (int c = 0; c < 4; c++) {
            float2 v0 = unpack2(acc0[2 * c]), v1 = unpack2(acc0[2 * c + 1]);
            *(float4*)(p0 + 128 * c) = make_float4(v0.x, v0.y, v1.x, v1.y);
            float2 w0 = unpack2(acc1[2 * c]), w1 = unpack2(acc1[2 * c + 1]);
            *(float4*)(p1 + 128 * c) = make_float4(w0.x, w0.y, w1.x, w1.y);
        }
    }
    if (lane == 0) {
        long base = ((long)b * PSPLIT + par) * 16;
        g_pml[base + h0]     = m0;
        g_pml[base + 8 + h0] = l0;
        g_pml[base + h1]     = m1;
        g_pml[base + 8 + h1] = l1;
    }
}

// ============================================================================
// Kernel D: FUSED merge + oproj. grid (32, 8) — y = head.
// out[b, y*64+d] = sum_j (w0[b]*pc0[b,y,j] + w1[b]*pc1[b,y,j]) * Wv[(y*64+d),j] + bv
// where w_s[b] = exp(m_s - M) / (sum_s exp(m_s - M) l_s)  (per b, head y).
// ============================================================================
__global__ void __launch_bounds__(256) k_oproj_fused(
    const float* __restrict__ B, const float* __restrict__ bias,
    float* __restrict__ out)
{
    __shared__ __align__(16) float Cs0[2][32][32];   // parity 0 A tile
    __shared__ __align__(16) float Cs1[2][32][32];   // parity 1 A tile
    __shared__ __align__(16) float Ws[2][64][32];
    __shared__ float wol0[32], wol1[32];
    const int tid = threadIdx.x;
    const int bB = blockIdx.x * 32;
    const int y  = blockIdx.y;                        // head
    const float* Bb = B + (long)y * 64 * 512;
    const int d0 = (tid >> 4) * 4;
    const int b0 = (tid & 15) * 2;

    // per-b merge weights for head y
    if (tid < 32) {
        int b = bB + tid;
        float m0 = g_pml[((long)b * PSPLIT + 0) * 16 + y];
        float l0 = g_pml[((long)b * PSPLIT + 0) * 16 + 8 + y];
        float m1 = g_pml[((long)b * PSPLIT + 1) * 16 + y];
        float l1 = g_pml[((long)b * PSPLIT + 1) * 16 + 8 + y];
        float M = fmaxf(m0, m1);
        float w0 = __expf(m0 - M), w1 = __expf(m1 - M);
        float inv = 1.0f / (w0 * l0 + w1 * l1);
        wol0[tid] = w0 * inv;
        wol1[tid] = w1 * inv;
    }

    u64 acc[2][4];
#pragma unroll
    for (int cb = 0; cb < 2; cb++)
#pragma unroll
        for (int dd = 0; dd < 4; dd++) acc[cb][dd] = 0ull;

    const int row = tid >> 3, cj = tid & 7;
    const long pc0_base = (((long)(bB + row) * PSPLIT + 0) * 8 + y) * 512;
    const long pc1_base = (((long)(bB + row) * PSPLIT + 1) * 8 + y) * 512;

    cp16(&Cs0[0][row][swz(cj, row)], (const float*)g_pc + pc0_base + cj * 4);
    cp16(&Cs1[0][row][swz(cj, row)], (const float*)g_pc + pc1_base + cj * 4);
#pragma unroll
    for (int i = 0; i < 2; i++) {
        int idx = tid + 256 * i;
        int d = idx >> 3, c8 = idx & 7;
        cp16(&Ws[0][d][swz(c8, d)], Bb + (long)d * 512 + c8 * 4);
    }
    cp_commit();
    __syncthreads();                       // wol visible (also pre-loop)

    // per-thread merge weights for its 2 rows
    u64 w0p[2], w1p[2];
#pragma unroll
    for (int cb = 0; cb < 2; cb++) {
        float a = wol0[b0 + cb], bb2 = wol1[b0 + cb];
        w0p[cb] = pack2(a, a);
        w1p[cb] = pack2(bb2, bb2);
    }

    for (int kc = 0; kc < 16; kc++) {
        const int buf = kc & 1;
        if (kc + 1 < 16) {
            cp16(&Cs0[buf ^ 1][row][swz(cj, row)],
                 (const float*)g_pc + pc0_base + (kc + 1) * 32 + cj * 4);
            cp16(&Cs1[buf ^ 1][row][swz(cj, row)],
                 (const float*)g_pc + pc1_base + (kc + 1) * 32 + cj * 4);
#pragma unroll
            for (int i = 0; i < 2; i++) {
                int idx = tid + 256 * i;
                int d = idx >> 3, c8 = idx & 7;
                cp16(&Ws[buf ^ 1][d][swz(c8, d)],
                     Bb + (long)d * 512 + (kc + 1) * 32 + c8 * 4);
            }
        }
        cp_commit();
        cp_wait1();
        __syncthreads();

#pragma unroll
        for (int jg = 0; jg < 8; jg++) {
            ulonglong2 wv[4];
#pragma unroll
            for (int dd = 0; dd < 4; dd++)
                wv[dd] = *(const ulonglong2*)&Ws[buf][d0 + dd][swz(jg, d0 + dd)];
#pragma unroll
            for (int cb = 0; cb < 2; cb++) {
                ulonglong2 c0 = *(const ulonglong2*)&Cs0[buf][b0 + cb][swz(jg, b0 + cb)];
                ulonglong2 c1 = *(const ulonglong2*)&Cs1[buf][b0 + cb][swz(jg, b0 + cb)];
                u64 t0 = 0ull, t1 = 0ull;
                ffma2(t0, w0p[cb], c0.x); ffma2(t0, w1p[cb], c1.x);
                ffma2(t1, w0p[cb], c0.y); ffma2(t1, w1p[cb], c1.y);
#pragma unroll
                for (int dd = 0; dd < 4; dd++) {
                    ffma2(acc[cb][dd], t0, wv[dd].x);
                    ffma2(acc[cb][dd], t1, wv[dd].y);
                }
            }
        }
        __syncthreads();
    }

    float4 bb = *(const float4*)&bias[y * 64 + d0];
#pragma unroll
    for (int cb = 0; cb < 2; cb++) {
        float v[4];
#pragma unroll
        for (int dd = 0; dd < 4; dd++) {
            float2 u = unpack2(acc[cb][dd]);
            v[dd] = u.x + u.y;
        }
        float4 o = make_float4(v[0] + bb.x, v[1] + bb.y, v[2] + bb.z, v[3] + bb.w);
        *(float4*)&out[(long)(bB + b0 + cb) * 512 + y * 64 + d0] = o;
    }
}

// ============================================================================
extern "C" void kernel_launch(void* const* d_in, const int* in_sizes, int n_in,
                              void* d_out, int out_size)
{
    const float* cur  = (const float*)d_in[0];   // [1024, 512]
    const float* prev = (const float*)d_in[1];   // [1024, 199, 512]
    const float* mask = (const float*)d_in[2];   // [1024, 200]
    const float* Wq   = (const float*)d_in[3];   // [512, 512]
    const float* bq   = (const float*)d_in[4];   // [512]
    const float* Wk   = (const float*)d_in[5];   // [512, 512]
    const float* bk   = (const float*)d_in[6];   // [512]
    const float* Wv   = (const float*)d_in[7];   // [512, 512]
    const float* bv   = (const float*)d_in[8];   // [512]
    float* out = (float*)d_out;                  // [1024, 512]

    // q = cur @ Wq^T + bq          (writes g_q internally)
    k_qproj<<<dim3(32, 8), 256>>>(cur, Wq, bq);
    // r[b,h,:] = Wk_h^T q_h        (g_q -> g_r)
    k_rproj<<<dim3(4, 32, 8), 256>>>(Wk);
    // lane-distinct attention      (-> g_pc, g_pml)
    k_attn <<<dim3(1024), 256>>>(cur, prev, mask, bk);
    // fused merge + out-projection (reads g_pc/g_pml internally)
    k_oproj_fused<<<dim3(32, 8), 256>>>(Wv, bv, out);
}

// round 16
// speedup vs baseline: 2.4780x; 1.0081x over previous
#include <cuda_runtime.h>
#include <math_constants.h>

#define BS   1024
#define DM   512
#define NH   8
#define DK   64
#define HIST 199
#define TT   200
#define TTILE 8
#define NBUF 3
#define NTILES 25
#define PSPLIT 2

// Scratch — referenced ONLY inside device code (host-side use passes the host
// shadow address; ATS makes it silently dereferenceable -> garbage).
__device__ float g_q[BS * DM];                     // 2 MB
__device__ float g_r[BS * NH * DM];                // 16 MB
__device__ float g_pc[BS * PSPLIT * NH * DM];      // 32 MB  unnormalized partial c
__device__ float g_pml[BS * PSPLIT * 16];          // 128 KB m[8], l[8] per (b,s)

typedef unsigned long long u64;

// ---- packed f32x2 helpers --------------------------------------------------
__device__ __forceinline__ u64 pack2(float x, float y) {
    u64 r; asm("mov.b64 %0, {%1, %2};" : "=l"(r) : "f"(x), "f"(y)); return r;
}
__device__ __forceinline__ float2 unpack2(u64 v) {
    float2 d; asm("mov.b64 {%0, %1}, %2;" : "=f"(d.x), "=f"(d.y) : "l"(v)); return d;
}
__device__ __forceinline__ void ffma2(u64& acc, u64 a, u64 b) {
    asm("fma.rn.f32x2 %0, %1, %2, %0;" : "+l"(acc) : "l"(a), "l"(b));
}
__device__ __forceinline__ void fmul2(u64& a, u64 b) {
    asm("mul.rn.f32x2 %0, %0, %1;" : "+l"(a) : "l"(b));
}
__device__ __forceinline__ void ldg16(const float* p, u64& a, u64& b) {
    asm volatile("ld.global.nc.v2.b64 {%0, %1}, [%2];" : "=l"(a), "=l"(b) : "l"(p));
}
__device__ __forceinline__ void cp16(void* smem_dst, const void* gsrc) {
    unsigned s = (unsigned)__cvta_generic_to_shared(smem_dst);
    asm volatile("cp.async.cg.shared.global [%0], [%1], 16;" :: "r"(s), "l"(gsrc));
}
__device__ __forceinline__ void cp_commit() { asm volatile("cp.async.commit_group;" ::: "memory"); }
__device__ __forceinline__ void cp_wait1()  { asm volatile("cp.async.wait_group 1;" ::: "memory"); }

__device__ __forceinline__ int swz(int cj, int row) { return 4 * (cj ^ ((row >> 1) & 7)); }

// ============================================================================
// Kernel A: qproj GEMM. 32b x 64d NT, K=512, grid (32,8).
// 3-buffer ring, ONE barrier per kc (16 total), prefetch lead 2.
// g_q[b, y*64+d] = sum_k cur[b,k] * Wq[(y*64+d)*512+k] + bq
// ============================================================================
__global__ void __launch_bounds__(256) k_qproj(
    const float* __restrict__ A, const float* __restrict__ B,
    const float* __restrict__ bias)
{
    __shared__ __align__(16) float Cs[3][32][32];   // 12 KB
    __shared__ __align__(16) float Ws[3][64][32];   // 24 KB
    const int tid = threadIdx.x;
    const int bB = blockIdx.x * 32;
    const int y  = blockIdx.y;
    const float* Bb = B + (long)y * 64 * 512;
    const int d0 = (tid >> 4) * 4;
    const int b0 = (tid & 15) * 2;

    u64 acc[2][4];
#pragma unroll
    for (int cb = 0; cb < 2; cb++)
#pragma unroll
        for (int dd = 0; dd < 4; dd++) acc[cb][dd] = 0ull;

    const int lrow = tid >> 3, lcj = tid & 7;
    #define QLOAD(buf, kc) do { \
        cp16(&Cs[buf][lrow][swz(lcj, lrow)], \
             A + (long)(bB + lrow) * 512 + (kc) * 32 + lcj * 4); \
        _Pragma("unroll") for (int i = 0; i < 2; i++) { \
            int idx = tid + 256 * i; int d = idx >> 3, cj = idx & 7; \
            cp16(&Ws[buf][d][swz(cj, d)], Bb + (long)d * 512 + (kc) * 32 + cj * 4); \
        } } while (0)

    QLOAD(0, 0); cp_commit();
    QLOAD(1, 1); cp_commit();

    for (int kc = 0; kc < 16; kc++) {
        const int buf = kc % 3;
        cp_wait1();                        // group kc complete (1 newer pending)
        __syncthreads();                   // the ONLY barrier per kc

        if (kc + 2 < 16) QLOAD((kc + 2) % 3, kc + 2);
        cp_commit();                       // uniform group count

#pragma unroll
        for (int jg = 0; jg < 8; jg++) {
            ulonglong2 wv[4], cv[2];
#pragma unroll
            for (int dd = 0; dd < 4; dd++)
                wv[dd] = *(const ulonglong2*)&Ws[buf][d0 + dd][swz(jg, d0 + dd)];
#pragma unroll
            for (int cb = 0; cb < 2; cb++)
                cv[cb] = *(const ulonglong2*)&Cs[buf][b0 + cb][swz(jg, b0 + cb)];
#pragma unroll
            for (int cb = 0; cb < 2; cb++)
#pragma unroll
                for (int dd = 0; dd < 4; dd++) {
                    ffma2(acc[cb][dd], cv[cb].x, wv[dd].x);
                    ffma2(acc[cb][dd], cv[cb].y, wv[dd].y);
                }
        }
    }

    float4 bb = *(const float4*)&bias[y * 64 + d0];
#pragma unroll
    for (int cb = 0; cb < 2; cb++) {
        float v[4];
#pragma unroll
        for (int dd = 0; dd < 4; dd++) {
            float2 u = unpack2(acc[cb][dd]);
            v[dd] = u.x + u.y;
        }
        float4 o = make_float4(v[0] + bb.x, v[1] + bb.y, v[2] + bb.z, v[3] + bb.w);
        *(float4*)&g_q[(long)(bB + b0 + cb) * 512 + y * 64 + d0] = o;
    }
}

// ============================================================================
// Kernel B: r[b,h,n] = sum_k q[b, h*64+k] * Wk[h*64+k, n]   (NN, K=64)
// ============================================================================
__global__ void __launch_bounds__(256) k_rproj(const float* __restrict__ Wk)
{
    __shared__ __align__(16) float Wks[64][128];
    __shared__ __align__(16) float qs[32][64];
    const int tid = threadIdx.x;
    const int nc = blockIdx.x;
    const int bB = blockIdx.y * 32;
    const int h  = blockIdx.z;

#pragma unroll
    for (int it = 0; it < 8; it++) {
        int idx = tid + 256 * it;
        int k = idx >> 5, n4 = (idx & 31) * 4;
        *(float4*)&Wks[k][n4] = *(const float4*)&Wk[(h * 64 + k) * 512 + nc * 128 + n4];
    }
#pragma unroll
    for (int it = 0; it < 2; it++) {
        int idx = tid + 256 * it;
        int bb = idx >> 4, k4 = (idx & 15) * 4;
        *(float4*)&qs[bb][k4] = *(const float4*)&g_q[(bB + bb) * 512 + h * 64 + k4];
    }
    __syncthreads();

    const int n0 = (tid & 31) * 4;
    const int b0 = (tid >> 5) * 4;
    u64 acc[4][2];
#pragma unroll
    for (int a = 0; a < 4; a++) { acc[a][0] = 0ull; acc[a][1] = 0ull; }

#pragma unroll
    for (int k = 0; k < 64; k++) {
        ulonglong2 w2 = *(const ulonglong2*)&Wks[k][n0];
#pragma unroll
        for (int cb = 0; cb < 4; cb++) {
            float x = qs[b0 + cb][k];
            u64 xx = pack2(x, x);
            ffma2(acc[cb][0], xx, w2.x);
            ffma2(acc[cb][1], xx, w2.y);
        }
    }
#pragma unroll
    for (int cb = 0; cb < 4; cb++) {
        float2 p0 = unpack2(acc[cb][0]), p1 = unpack2(acc[cb][1]);
        float4 o = make_float4(p0.x, p0.y, p1.x, p1.y);
        *(float4*)&g_r[((bB + b0 + cb) * 8 + h) * 512 + nc * 128 + n0] = o;
    }
}

// ============================================================================
// Kernel C: LANE-DISTINCT attention (unchanged from R15 — measured best).
// ============================================================================
__device__ __forceinline__ void prefetch_tile(
    float* dst, const float* __restrict__ prevb, const float* __restrict__ curb,
    int tile, int tid)
{
#pragma unroll
    for (int i = 0; i < 4; i++) {
        int idx = tid + 256 * i;        // 1024 float4 = 8 rows x 512 floats
        int tr = idx >> 7;
        int c = (idx & 127) * 4;
        int gt = tile * TTILE + tr;     // <= 199 (25*8 = 200 exact)
        const float* src = (gt < HIST) ? (prevb + (long)gt * 512 + c) : (curb + c);
        cp16(dst + tr * 512 + c, src);
    }
}

__device__ __forceinline__ float bfly_sum(float s) {
#pragma unroll
    for (int o = 16; o; o >>= 1) s += __shfl_xor_sync(0xffffffffu, s, o);
    return s;
}

__global__ void __launch_bounds__(256, 2) k_attn(
    const float* __restrict__ cur, const float* __restrict__ prev,
    const float* __restrict__ mask, const float* __restrict__ bk)
{
    __shared__ __align__(16) float xb[NBUF][TTILE][DM];   // 48 KB
    __shared__ float mask_s[TT];
    __shared__ float sb_s[8];

    const int tid = threadIdx.x;
    const int b = blockIdx.x;
    const int w = tid >> 5, lane = tid & 31;
    const int hp = w & 3, par = w >> 2;
    const int h0 = 2 * hp, h1 = 2 * hp + 1;

    const float* prevb = prev + (long)b * HIST * 512;
    const float* curb  = cur  + (long)b * 512;

    if (tid < TT) mask_s[tid] = mask[b * TT + tid];
    {   // sb[h] = q[b,h,:]·bk[h,:]; warp w computes head w
        float q1 = g_q[b * 512 + w * 64 + lane];
        float q2 = g_q[b * 512 + w * 64 + 32 + lane];
        float sv = q1 * bk[w * 64 + lane] + q2 * bk[w * 64 + 32 + lane];
        sv = bfly_sum(sv);
        if (lane == 0) sb_s[w] = sv;
    }

    // rf: r[b, h, 4*lane + 128*c] for both heads (16 distinct floats each)
    u64 rf0[8], rf1[8];
    {
        const float* rp0 = &g_r[((long)b * 8 + h0) * 512 + 4 * lane];
        const float* rp1 = &g_r[((long)b * 8 + h1) * 512 + 4 * lane];
#pragma unroll
        for (int c = 0; c < 4; c++) {
            ldg16(rp0 + 128 * c, rf0[2 * c], rf0[2 * c + 1]);
            ldg16(rp1 + 128 * c, rf1[2 * c], rf1[2 * c + 1]);
        }
    }
    u64 acc0[8], acc1[8];
#pragma unroll
    for (int i = 0; i < 8; i++) { acc0[i] = 0ull; acc1[i] = 0ull; }
    float m0 = -CUDART_INF_F, l0 = 0.f;
    float m1 = -CUDART_INF_F, l1 = 0.f;

    // prime 2 tiles
#pragma unroll
    for (int i = 0; i < 2; i++) {
        prefetch_tile(&xb[i][0][0], prevb, curb, i, tid);
        cp_commit();
    }
    __syncthreads();                       // sb_s / mask_s visible
    const float sb0 = sb_s[h0];
    const float sb1 = sb_s[h1];

    for (int tile = 0; tile < NTILES; tile++) {
        const int buf = tile % NBUF;
        cp_wait1();                        // tile's group complete (1 newer pend)
        __syncthreads();                   // the ONLY barrier per tile

        if (tile + 2 < NTILES)
            prefetch_tile(&xb[(tile + 2) % NBUF][0][0], prevb, curb, tile + 2, tid);
        cp_commit();                       // uniform group count

#pragma unroll
        for (int sub = 0; sub < 2; sub++) {
            const int tA = 4 * sub + par;
            const float* rA = &xb[buf][tA][4 * lane];
            const float* rB = &xb[buf][tA + 2][4 * lane];
            u64 xA[8], xB[8];
#pragma unroll
            for (int c = 0; c < 4; c++) {
                ulonglong2 vA = *(const ulonglong2*)(rA + 128 * c);
                ulonglong2 vB = *(const ulonglong2*)(rB + 128 * c);
                xA[2 * c] = vA.x; xA[2 * c + 1] = vA.y;
                xB[2 * c] = vB.x; xB[2 * c + 1] = vB.y;
            }

            u64 a00 = 0ull, a01 = 0ull, a10 = 0ull, a11 = 0ull;
            u64 b00 = 0ull, b01 = 0ull, b10 = 0ull, b11 = 0ull;
#pragma unroll
            for (int i = 0; i < 8; i += 2) {
                ffma2(a00, rf0[i], xA[i]);   ffma2(a01, rf0[i + 1], xA[i + 1]);
                ffma2(a10, rf1[i], xA[i]);   ffma2(a11, rf1[i + 1], xA[i + 1]);
                ffma2(b00, rf0[i], xB[i]);   ffma2(b01, rf0[i + 1], xB[i + 1]);
                ffma2(b10, rf1[i], xB[i]);   ffma2(b11, rf1[i + 1], xB[i + 1]);
            }
            float2 u;
            u = unpack2(a00); float sA0 = u.x + u.y; u = unpack2(a01); sA0 += u.x + u.y;
            u = unpack2(a10); float sA1 = u.x + u.y; u = unpack2(a11); sA1 += u.x + u.y;
            u = unpack2(b00); float sB0 = u.x + u.y; u = unpack2(b01); sB0 += u.x + u.y;
            u = unpack2(b10); float sB1 = u.x + u.y; u = unpack2(b11); sB1 += u.x + u.y;
            sA0 = bfly_sum(sA0); sA1 = bfly_sum(sA1);
            sB0 = bfly_sum(sB0); sB1 = bfly_sum(sB1);

            const int gtA = tile * TTILE + tA;
            const int gtB = gtA + 2;
            float lgA0 = (sA0 + sb0) * 0.125f + mask_s[gtA];
            float lgB0 = (sB0 + sb0) * 0.125f + mask_s[gtB];
            float lgA1 = (sA1 + sb1) * 0.125f + mask_s[gtA];
            float lgB1 = (sB1 + sb1) * 0.125f + mask_s[gtB];

            float mx0 = fmaxf(lgA0, lgB0);
            if (mx0 > m0) {
                float scl = __expf(m0 - mx0);  // first: exp(-inf) = 0
                u64 sclp = pack2(scl, scl);
#pragma unroll
                for (int i = 0; i < 8; i++) fmul2(acc0[i], sclp);
                l0 *= scl; m0 = mx0;
            }
            float pA0 = __expf(lgA0 - m0), pB0 = __expf(lgB0 - m0);
            l0 += pA0 + pB0;

            float mx1 = fmaxf(lgA1, lgB1);
            if (mx1 > m1) {
                float scl = __expf(m1 - mx1);
                u64 sclp = pack2(scl, scl);
#pragma unroll
                for (int i = 0; i < 8; i++) fmul2(acc1[i], sclp);
                l1 *= scl; m1 = mx1;
            }
            float pA1 = __expf(lgA1 - m1), pB1 = __expf(lgB1 - m1);
            l1 += pA1 + pB1;

            u64 pvA0 = pack2(pA0, pA0), pvB0 = pack2(pB0, pB0);
            u64 pvA1 = pack2(pA1, pA1), pvB1 = pack2(pB1, pB1);
#pragma unroll
            for (int i = 0; i < 8; i++) {
                ffma2(acc0[i], pvA0, xA[i]);
                ffma2(acc1[i], pvA1, xA[i]);
                ffma2(acc0[i], pvB0, xB[i]);
                ffma2(acc1[i], pvB1, xB[i]);
            }
        }
    }

    // ---- write UNNORMALIZED parity partials + (m, l) ----
    {
        float* p0 = &g_pc[(((long)b * PSPLIT + par) * 8 + h0) * 512 + 4 * lane];
        float* p1 = &g_pc[(((long)b * PSPLIT + par) * 8 + h1) * 512 + 4 * lane];
#pragma unroll
        for (int c = 0; c < 4; c++) {
            float2 v0 = unpack2(acc0[2 * c]), v1 = unpack2(acc0[2 * c + 1]);
            *(float4*)(p0 + 128 * c) = make_float4(v0.x, v0.y, v1.x, v1.y);
            float2 w0 = unpack2(acc1[2 * c]), w1 = unpack2(acc1[2 * c + 1]);
            *(float4*)(p1 + 128 * c) = make_float4(w0.x, w0.y, w1.x, w1.y);
        }
    }
    if (lane == 0) {
        long base = ((long)b * PSPLIT + par) * 16;
        g_pml[base + h0]     = m0;
        g_pml[base + 8 + h0] = l0;
        g_pml[base + h1]     = m1;
        g_pml[base + 8 + h1] = l1;
    }
}

// ============================================================================
// Kernel D: FUSED merge + oproj. grid (32, 8) — y = head.
// 3-buffer ring, ONE barrier per kc. Merge weights computed per-thread from
// g_pml directly (no smem/barrier). Cs packs both parities: [3][32][64].
// out[b, y*64+d] = sum_j (w0*pc0 + w1*pc1)[b,y,j] * Wv[(y*64+d),j] + bv
// ============================================================================
__global__ void __launch_bounds__(256) k_oproj_fused(
    const float* __restrict__ B, const float* __restrict__ bias,
    float* __restrict__ out)
{
    __shared__ __align__(16) float Cs[3][32][64];   // 24 KB (parity p at +32p)
    __shared__ __align__(16) float Ws[3][64][32];   // 24 KB
    const int tid = threadIdx.x;
    const int bB = blockIdx.x * 32;
    const int y  = blockIdx.y;                       // head
    const float* Bb = B + (long)y * 64 * 512;
    const int d0 = (tid >> 4) * 4;
    const int b0 = (tid & 15) * 2;

    // per-thread merge weights for its 2 rows (redundant LDG -> L1 broadcast)
    u64 w0p[2], w1p[2];
#pragma unroll
    for (int cb = 0; cb < 2; cb++) {
        int b = bB + b0 + cb;
        float m0 = g_pml[((long)b * PSPLIT + 0) * 16 + y];
        float l0 = g_pml[((long)b * PSPLIT + 0) * 16 + 8 + y];
        float m1 = g_pml[((long)b * PSPLIT + 1) * 16 + y];
        float l1 = g_pml[((long)b * PSPLIT + 1) * 16 + 8 + y];
        float M = fmaxf(m0, m1);
        float e0 = __expf(m0 - M), e1 = __expf(m1 - M);
        float inv = 1.0f / (e0 * l0 + e1 * l1);
        w0p[cb] = pack2(e0 * inv, e0 * inv);
        w1p[cb] = pack2(e1 * inv, e1 * inv);
    }

    u64 acc[2][4];
#pragma unroll
    for (int cb = 0; cb < 2; cb++)
#pragma unroll
        for (int dd = 0; dd < 4; dd++) acc[cb][dd] = 0ull;

    // loaders: Cs 512 float4 (2/thread: idx = tid + 256i, p = idx>>8,
    // row = (idx>>3)&31, cj = idx&7); Ws 512 float4 (2/thread).
    #define OLOAD(buf, kc) do { \
        _Pragma("unroll") for (int i = 0; i < 2; i++) { \
            int idx = tid + 256 * i; \
            int p = idx >> 8, row = (idx >> 3) & 31, cj = idx & 7; \
            long base = (((long)(bB + row) * PSPLIT + p) * 8 + y) * 512; \
            cp16(&Cs[buf][row][32 * p + swz(cj, row)], \
                 (const float*)g_pc + base + (kc) * 32 + cj * 4); \
            int d = idx >> 3, c8 = idx & 7; \
            cp16(&Ws[buf][d][swz(c8, d)], Bb + (long)d * 512 + (kc) * 32 + c8 * 4); \
        } } while (0)

    OLOAD(0, 0); cp_commit();
    OLOAD(1, 1); cp_commit();

    for (int kc = 0; kc < 16; kc++) {
        const int buf = kc % 3;
        cp_wait1();                        // group kc complete
        __syncthreads();                   // the ONLY barrier per kc

        if (kc + 2 < 16) OLOAD((kc + 2) % 3, kc + 2);
        cp_commit();                       // uniform group count

#pragma unroll
        for (int jg = 0; jg < 8; jg++) {
            ulonglong2 wv[4];
#pragma unroll
            for (int dd = 0; dd < 4; dd++)
                wv[dd] = *(const ulonglong2*)&Ws[buf][d0 + dd][swz(jg, d0 + dd)];
#pragma unroll
            for (int cb = 0; cb < 2; cb++) {
                int rw = b0 + cb;
                ulonglong2 c0 = *(const ulonglong2*)&Cs[buf][rw][swz(jg, rw)];
                ulonglong2 c1 = *(const ulonglong2*)&Cs[buf][rw][32 + swz(jg, rw)];
                u64 t0 = 0ull, t1 = 0ull;
                ffma2(t0, w0p[cb], c0.x); ffma2(t0, w1p[cb], c1.x);
                ffma2(t1, w0p[cb], c0.y); ffma2(t1, w1p[cb], c1.y);
#pragma unroll
                for (int dd = 0; dd < 4; dd++) {
                    ffma2(acc[cb][dd], t0, wv[dd].x);
                    ffma2(acc[cb][dd], t1, wv[dd].y);
                }
            }
        }
    }

    float4 bb = *(const float4*)&bias[y * 64 + d0];
#pragma unroll
    for (int cb = 0; cb < 2; cb++) {
        float v[4];
#pragma unroll
        for (int dd = 0; dd < 4; dd++) {
            float2 u = unpack2(acc[cb][dd]);
            v[dd] = u.x + u.y;
        }
        float4 o = make_float4(v[0] + bb.x, v[1] + bb.y, v[2] + bb.z, v[3] + bb.w);
        *(float4*)&out[(long)(bB + b0 + cb) * 512 + y * 64 + d0] = o;
    }
}

// ============================================================================
extern "C" void kernel_launch(void* const* d_in, const int* in_sizes, int n_in,
                              void* d_out, int out_size)
{
    const float* cur  = (const float*)d_in[0];   // [1024, 512]
    const float* prev = (const float*)d_in[1];   // [1024, 199, 512]
    const float* mask = (const float*)d_in[2];   // [1024, 200]
    const float* Wq   = (const float*)d_in[3];   // [512, 512]
    const float* bq   = (const float*)d_in[4];   // [512]
    const float* Wk   = (const float*)d_in[5];   // [512, 512]
    const float* bk   = (const float*)d_in[6];   // [512]
    const float* Wv   = (const float*)d_in[7];   // [512, 512]
    const float* bv   = (const float*)d_in[8];   // [512]
    float* out = (float*)d_out;                  // [1024, 512]

    // q = cur @ Wq^T + bq          (writes g_q internally)
    k_qproj<<<dim3(32, 8), 256>>>(cur, Wq, bq);
    // r[b,h,:] = Wk_h^T q_h        (g_q -> g_r)
    k_rproj<<<dim3(4, 32, 8), 256>>>(Wk);
    // lane-distinct attention      (-> g_pc, g_pml)
    k_attn <<<dim3(1024), 256>>>(cur, prev, mask, bk);
    // fused merge + out-projection (reads g_pc/g_pml internally)
    k_oproj_fused<<<dim3(32, 8), 256>>>(Wv, bv, out);
}